// round 13
// baseline (speedup 1.0000x reference)
#include <cuda_runtime.h>
#include <cuda_fp16.h>
#include <math.h>
#include <stdint.h>

// ---------------- problem constants ----------------
#define B_  32
#define L_  1024
#define DIN 16
#define DM  512
#define DI  1024          // EXP*DM
#define H_  16            // DI/P
#define P_  64
#define N_  64
#define DCONV 4
#define CONV_DIM 1152     // DI + 2N
#define DPROJ 2192        // 2*DI + 2*N + H
#define REST 1168         // CONV_DIM + H
#define WPAD 1280         // padded N for Win slice
#define NCLS 10
#define BL  (B_*L_)       // 32768
#define EPS 1e-5f

// ---------------- scratch (static device globals; no allocations) -------------
__device__ uint32_t g_h1h[BL*64];            // [BL][64]
__device__ uint32_t g_h2h[(size_t)BL*128];   // [BL][128]
__device__ uint32_t g_uh [(size_t)BL*256];   // [BL][256]
// packed half2 weights, pair-major k: [kp][n]
__device__ uint32_t g_w2th[64*256];
__device__ uint32_t g_w3th[128*512];
__device__ uint32_t g_winth[(size_t)256*WPAD];
// fp32 intermediates
__device__ float g_xbcr[(size_t)BL*REST];
__device__ float g_Bm [BL*N_];
__device__ float g_Cm [B_*N_];
__device__ float g_dtp[B_*H_*L_];
__device__ float g_beta[BL];
__device__ float g_wbuf[B_*H_*L_];           // w = coef*beta
__device__ int   g_need [B_*H_*8];           // per (bh, chunk) compute flag
__device__ int   g_pflag[B_*8*8];            // per (b, chunk, nblock) produce flag
__device__ float g_y  [B_*DI];
__device__ float g_z  [B_*DI];

// ---------------- helpers ------------------------------------------------------
__device__ __forceinline__ uint32_t pack_h2(float a, float b) {
    __half2 h = __floats2half2_rn(a, b);
    return *(uint32_t*)&h;
}
__device__ __forceinline__ void mma_f16(float* c, const uint32_t* a, const uint32_t* b) {
    asm volatile(
        "mma.sync.aligned.m16n8k16.row.col.f32.f16.f16.f32 "
        "{%0,%1,%2,%3}, {%4,%5,%6,%7}, {%8,%9}, {%0,%1,%2,%3};\n"
        : "+f"(c[0]), "+f"(c[1]), "+f"(c[2]), "+f"(c[3])
        : "r"(a[0]), "r"(a[1]), "r"(a[2]), "r"(a[3]), "r"(b[0]), "r"(b[1]));
}
__device__ __forceinline__ void ldmx4(uint32_t& r0, uint32_t& r1, uint32_t& r2, uint32_t& r3,
                                      uint32_t saddr) {
    asm volatile("ldmatrix.sync.aligned.m8n8.x4.shared.b16 {%0,%1,%2,%3}, [%4];"
                 : "=r"(r0), "=r"(r1), "=r"(r2), "=r"(r3) : "r"(saddr));
}
__device__ __forceinline__ void cp16(uint32_t saddr, const void* g) {
    asm volatile("cp.async.cg.shared.global [%0], [%1], 16;\n" :: "r"(saddr), "l"(g));
}
__device__ __forceinline__ void cp_commit() { asm volatile("cp.async.commit_group;\n"); }
template<int n> __device__ __forceinline__ void cp_wait() {
    asm volatile("cp.async.wait_group %0;\n" :: "n"(n));
}
__device__ __forceinline__ uint32_t smem_u32(const void* p) {
    uint32_t a;
    asm("{ .reg .u64 t; cvta.to.shared.u64 t, %1; cvt.u32.u64 %0, t; }" : "=r"(a) : "l"(p));
    return a;
}

#define SSTRIDE 136
#define STG 4
#define AW 2048
#define BW (16 * SSTRIDE)
#define SMEM_BYTES (STG * (AW + BW) * 4)   // 67584

// =============================================================================
// FP16 tensor-core GEMM (m16n8k16, fp32 accum), cp.async 4-stage pipeline.
// (R10-proven layout; bn0 = n-block offset, pflag = optional CTA skip mask)
// =============================================================================
template<int RELU, int OUTH>
__global__ __launch_bounds__(256, 2) void hgemm_kernel(
    const uint32_t* __restrict__ A, int lda,
    const uint32_t* __restrict__ W, int ldw,
    const float* __restrict__ bias,
    float* __restrict__ C, int ldc,
    int N, int Kh, int bn0, const int* __restrict__ pflag)
{
    if (pflag) {
        int b = blockIdx.y >> 3, chunk = blockIdx.y & 7;
        if (!pflag[(b * 8 + chunk) * 8 + blockIdx.x]) return;
    }
    extern __shared__ uint32_t smem[];
    uint32_t* Asm = smem;
    uint32_t* Bsm = smem + STG * AW;

    const int bm = blockIdx.y * 128;
    const int bn = (blockIdx.x + bn0) * 128;
    const int tid = threadIdx.x;
    const int warp = tid >> 5;
    const int lane = tid & 31;
    const int warp_m = (warp & 1) * 64;
    const int warp_n = (warp >> 1) * 32;
    const int lg = lane >> 2;
    const int lr = lane & 3;

    const int am0 = tid >> 2;
    const int akq = tid & 3;
    const int aw0 = am0 * 16 + ((akq ^ (am0 & 3)) << 2);
    const int am1 = am0 + 64;
    const int aw1 = am1 * 16 + ((akq ^ (am1 & 3)) << 2);
    const int bk0 = tid >> 5;
    const int bn40 = (tid & 31) * 4;
    const int bk1 = bk0 + 8;

    const int q  = lane >> 3;
    const int rr = lane & 7;
    const int mlo = rr + (q & 1) * 8;
    const int qh = q >> 1;
    uint32_t asw[4][2];
    #pragma unroll
    for (int mi = 0; mi < 4; mi++) {
        int m = warp_m + mi * 16 + mlo;
        #pragma unroll
        for (int ks = 0; ks < 2; ks++)
            asw[mi][ks] = m * 16 + (((ks * 2 + qh) ^ (m & 3)) << 2);
    }
    const uint32_t as_base = smem_u32(Asm);
    const uint32_t bs_base = smem_u32(Bsm);

    float acc[4][4][4];
    #pragma unroll
    for (int i = 0; i < 4; i++)
        #pragma unroll
        for (int j = 0; j < 4; j++)
            #pragma unroll
            for (int r = 0; r < 4; r++) acc[i][j][r] = 0.f;

    const int T = Kh >> 5;

    auto issue = [&](int t, int s) {
        const int k0 = t * 16;
        cp16(as_base + (s * AW + aw0) * 4, &A[(size_t)(bm + am0) * lda + k0 + akq * 4]);
        cp16(as_base + (s * AW + aw1) * 4, &A[(size_t)(bm + am1) * lda + k0 + akq * 4]);
        cp16(bs_base + (s * BW + bk0 * SSTRIDE + bn40) * 4, &W[(size_t)(k0 + bk0) * ldw + bn + bn40]);
        cp16(bs_base + (s * BW + bk1 * SSTRIDE + bn40) * 4, &W[(size_t)(k0 + bk1) * ldw + bn + bn40]);
        cp_commit();
    };

    #pragma unroll
    for (int i = 0; i < STG - 1; i++)
        if (i < T) issue(i, i);

    for (int t = 0; t < T; t++) {
        cp_wait<STG - 2>();
        __syncthreads();
        const int s = t & (STG - 1);
        const uint32_t* Bst = Bsm + s * BW;

        #pragma unroll
        for (int ks = 0; ks < 2; ks++) {
            const int kp = ks * 8;
            uint32_t af[4][4], bf[4][2];
            #pragma unroll
            for (int mi = 0; mi < 4; mi++)
                ldmx4(af[mi][0], af[mi][1], af[mi][2], af[mi][3],
                      as_base + (s * AW + asw[mi][ks]) * 4);
            #pragma unroll
            for (int ni = 0; ni < 4; ni++) {
                const int n0 = warp_n + ni * 8;
                bf[ni][0] = Bst[(kp + lr)     * SSTRIDE + n0 + lg];
                bf[ni][1] = Bst[(kp + 4 + lr) * SSTRIDE + n0 + lg];
            }
            #pragma unroll
            for (int mi = 0; mi < 4; mi++)
                #pragma unroll
                for (int ni = 0; ni < 4; ni++)
                    mma_f16(acc[mi][ni], af[mi], bf[ni]);
        }

        if (t + STG - 1 < T) issue(t + STG - 1, (t + STG - 1) & (STG - 1));
    }

    #pragma unroll
    for (int mi = 0; mi < 4; mi++) {
        #pragma unroll
        for (int half = 0; half < 2; half++) {
            const int gr = bm + warp_m + mi * 16 + lg + half * 8;
            #pragma unroll
            for (int ni = 0; ni < 4; ni++) {
                const int gn = bn + warp_n + ni * 8 + lr * 2;
                float v0 = acc[mi][ni][half * 2 + 0];
                float v1 = acc[mi][ni][half * 2 + 1];
                if (bias) { v0 += bias[gn]; v1 += bias[gn + 1]; }
                if (RELU) { v0 = fmaxf(v0, 0.f); v1 = fmaxf(v1, 0.f); }
                if (OUTH) {
                    ((uint32_t*)C)[(size_t)gr * ldc + (gn >> 1)] = pack_h2(v0, v1);
                } else {
                    if (gn >= N) continue;
                    *(float2*)&C[(size_t)gr * ldc + gn] = make_float2(v0, v1);
                }
            }
        }
    }
}

// ---------------- weight prep: pack to half2 pair-major, pad Win slice ---------
__global__ void prep_kernel(const float* __restrict__ W2,
                            const float* __restrict__ W3,
                            const float* __restrict__ Win)
{
    int i = blockIdx.x * 256 + threadIdx.x;
    if (i < 64 * 256) {
        int kp = i >> 8, n = i & 255;
        g_w2th[i] = pack_h2(W2[(2 * kp) * 256 + n], W2[(2 * kp + 1) * 256 + n]);
    }
    if (i < 128 * 512) {
        int kp = i >> 9, n = i & 511;
        g_w3th[i] = pack_h2(W3[(2 * kp) * 512 + n], W3[(2 * kp + 1) * 512 + n]);
    }
    if (i < 256 * WPAD) {
        int kp = i / WPAD, n = i % WPAD;
        g_winth[i] = (n < REST)
            ? pack_h2(Win[(size_t)(2 * kp) * DPROJ + DI + n],
                      Win[(size_t)(2 * kp + 1) * DPROJ + DI + n])
            : 0u;
    }
}

// ---------------- G1: fp32 fma SGEMM, packed-half output -----------------------
__global__ void sgemm1_kernel(const float* __restrict__ A,
                              const float* __restrict__ W,
                              const float* __restrict__ bias,
                              uint32_t* __restrict__ Ch)
{
    __shared__ float As[8][128];
    __shared__ float Bs[8][128];
    const int bm = blockIdx.y * 128;
    const int tid = threadIdx.x;
    const int tr = tid >> 4;
    const int tc = tid & 15;

    float acc[8][8];
    #pragma unroll
    for (int i = 0; i < 8; i++)
        #pragma unroll
        for (int j = 0; j < 8; j++) acc[i][j] = 0.f;

    for (int k0 = 0; k0 < DIN; k0 += 8) {
        {
            int e = tid * 4;
            int r = e >> 3, kk = e & 7;
            float4 av = *(const float4*)&A[(size_t)(bm + r) * DIN + k0 + kk];
            As[kk + 0][r] = av.x; As[kk + 1][r] = av.y;
            As[kk + 2][r] = av.z; As[kk + 3][r] = av.w;
        }
        {
            int e = tid * 4;
            int kk = e >> 7, n = e & 127;
            const float* wrow = W + (size_t)(k0 + kk) * 128;
            #pragma unroll
            for (int i = 0; i < 4; i++) Bs[kk][n + i] = wrow[n + i];
        }
        __syncthreads();
        #pragma unroll
        for (int kk = 0; kk < 8; kk++) {
            float4 a0 = *(const float4*)&As[kk][tr * 4];
            float4 a1 = *(const float4*)&As[kk][64 + tr * 4];
            float4 b0 = *(const float4*)&Bs[kk][tc * 4];
            float4 b1 = *(const float4*)&Bs[kk][64 + tc * 4];
            float a[8] = {a0.x,a0.y,a0.z,a0.w,a1.x,a1.y,a1.z,a1.w};
            float b[8] = {b0.x,b0.y,b0.z,b0.w,b1.x,b1.y,b1.z,b1.w};
            #pragma unroll
            for (int i = 0; i < 8; i++)
                #pragma unroll
                for (int j = 0; j < 8; j++) acc[i][j] = fmaf(a[i], b[j], acc[i][j]);
        }
        __syncthreads();
    }
    #pragma unroll
    for (int i = 0; i < 8; i++) {
        int gr = bm + ((i < 4) ? (tr * 4 + i) : (64 + tr * 4 + i - 4));
        #pragma unroll
        for (int j = 0; j < 8; j += 2) {
            int gn = (j < 4) ? (tc * 4 + j) : (64 + tc * 4 + j - 4);
            float v0 = fmaxf(acc[i][j]     + bias[gn],     0.f);
            float v1 = fmaxf(acc[i][j + 1] + bias[gn + 1], 0.f);
            Ch[(size_t)gr * 64 + (gn >> 1)] = pack_h2(v0, v1);
        }
    }
}

// ---------------- activation helpers ------------------------------------------
__device__ __forceinline__ float siluf(float x) { return x / (1.f + __expf(-x)); }
__device__ __forceinline__ float softplusf(float x) {
    return (x > 0.f) ? x + log1pf(__expf(-x)) : log1pf(__expf(x));
}

// ---------------- dt projection: dtp = softplus(u . win_dt + bias) -------------
// u rows shared across 16 heads via smem; weights (half-rounded, same as mma).
__global__ void dtproj_kernel(const uint32_t* __restrict__ uh,
                              const uint32_t* __restrict__ winth,
                              const float* __restrict__ dt_bias,
                              float* __restrict__ dtp)
{
    __shared__ uint32_t ws[256 * 16];   // [kp][h]
    __shared__ uint32_t us[8][256];
    int tid = threadIdx.x;              // 128
    int row0 = blockIdx.x * 8;
    for (int i = tid; i < 256 * 16; i += 128) {
        int kp = i >> 4, h = i & 15;
        ws[i] = winth[(size_t)kp * WPAD + 1152 + h];
    }
    for (int i = tid; i < 8 * 256; i += 128) {
        int r = i >> 8, kp = i & 255;
        us[r][kp] = uh[(size_t)(row0 + r) * 256 + kp];
    }
    __syncthreads();
    int r = tid >> 4;
    int h = tid & 15;
    float acc = 0.f;
    #pragma unroll 8
    for (int kp = 0; kp < 256; kp++) {
        float2 a = __half22float2(*(__half2*)&us[r][kp]);
        float2 w = __half22float2(*(__half2*)&ws[kp * 16 + h]);
        acc = fmaf(a.x, w.x, acc);
        acc = fmaf(a.y, w.y, acc);
    }
    int row = row0 + r;
    int b = row >> 10, l = row & 1023;
    dtp[(size_t)(b * H_ + h) * L_ + l] = softplusf(acc + dt_bias[h]);
}

// ---------------- conv for B/C channels only (128 channels) --------------------
#define LCH 128
__global__ void conv_kernel(const float* __restrict__ xbcr,
                            const float* __restrict__ conv_w,
                            const float* __restrict__ conv_b,
                            float* __restrict__ Bm,
                            float* __restrict__ Cm)
{
    int c  = DI + threadIdx.x;          // 1024..1151
    int b  = blockIdx.y;
    int l0 = blockIdx.z * LCH;
    const float* col = xbcr + (size_t)b * L_ * REST + c;

    float w0 = conv_w[c * 4 + 0], w1 = conv_w[c * 4 + 1];
    float w2 = conv_w[c * 4 + 2], w3 = conv_w[c * 4 + 3];
    float cb = conv_b[c];

    if (c >= DI + N_) {
        if (l0 + LCH != L_) return;
        int l = L_ - 1;
        float acc = cb + w0 * col[(size_t)(l - 3) * REST] + w1 * col[(size_t)(l - 2) * REST]
                       + w2 * col[(size_t)(l - 1) * REST] + w3 * col[(size_t)l * REST];
        Cm[b * N_ + (c - DI - N_)] = siluf(acc);
        return;
    }
    float xm3 = (l0 - 3 >= 0) ? col[(size_t)(l0 - 3) * REST] : 0.f;
    float xm2 = (l0 - 2 >= 0) ? col[(size_t)(l0 - 2) * REST] : 0.f;
    float xm1 = (l0 - 1 >= 0) ? col[(size_t)(l0 - 1) * REST] : 0.f;
    float* orow = Bm + (size_t)(b * L_ + l0) * N_ + (c - DI);
    #pragma unroll 4
    for (int l = l0; l < l0 + LCH; l++) {
        float xl = col[(size_t)l * REST];
        float acc = fmaf(w0, xm3, fmaf(w1, xm2, fmaf(w2, xm1, fmaf(w3, xl, cb))));
        *orow = siluf(acc);
        orow += N_;
        xm3 = xm2; xm2 = xm1; xm1 = xl;
    }
}

// ---------------- beta[b,t] = B_t . C_last -------------------------------------
__global__ void beta_kernel(const float* __restrict__ Bm,
                            const float* __restrict__ Cm,
                            float* __restrict__ beta)
{
    int row = blockIdx.x * 8 + (threadIdx.x >> 5);
    int b = row >> 10;
    int lane = threadIdx.x & 31;
    float s = Bm[(size_t)row * N_ + lane]      * Cm[b * N_ + lane]
            + Bm[(size_t)row * N_ + 32 + lane] * Cm[b * N_ + 32 + lane];
    #pragma unroll
    for (int o = 16; o; o >>= 1) s += __shfl_down_sync(0xffffffffu, s, o);
    if (lane == 0) beta[row] = s;
}

// ---------------- fused suffix scan + w = coef*beta + need flags ----------------
__global__ void scanw_kernel(const float* __restrict__ dtp,
                             const float* __restrict__ A_log,
                             const float* __restrict__ beta,
                             float* __restrict__ wbuf,
                             int* __restrict__ need)
{
    int bh = blockIdx.x;
    int h = bh & (H_ - 1);
    int b = bh >> 4;
    float a = expf(A_log[h]);
    __shared__ float part[256];
    __shared__ float off[256];
    const float* row = dtp + (size_t)bh * L_;
    int t0 = threadIdx.x * 4;
    float v0 = row[t0], v1 = row[t0 + 1], v2 = row[t0 + 2], v3 = row[t0 + 3];
    part[threadIdx.x] = v0 + v1 + v2 + v3;
    __syncthreads();
    if (threadIdx.x == 0) {
        float s = 0.f;
        for (int i = 255; i >= 0; i--) { off[i] = s; s += part[i]; }
    }
    __syncthreads();
    float S3 = off[threadIdx.x];
    float S2 = S3 + v3;
    float S1 = S2 + v2;
    float S0 = S1 + v1;
    const float* brow = beta + (size_t)b * L_;
    float c0 = expf(-a * S0) * v0;
    float c1 = expf(-a * S1) * v1;
    float c2 = expf(-a * S2) * v2;
    float c3 = expf(-a * S3) * v3;
    float w0v = c0 * brow[t0 + 0];
    float w1v = c1 * brow[t0 + 1];
    float w2v = c2 * brow[t0 + 2];
    float w3v = c3 * brow[t0 + 3];
    float* wrow = wbuf + (size_t)bh * L_;
    wrow[t0 + 0] = w0v; wrow[t0 + 1] = w1v;
    wrow[t0 + 2] = w2v; wrow[t0 + 3] = w3v;
    int nz = (w0v != 0.f) | (w1v != 0.f) | (w2v != 0.f) | (w3v != 0.f);
    int any = __any_sync(0xffffffffu, nz);
    int c = threadIdx.x >> 5;            // warp c == chunk c (t = 128c..128c+127)
    if ((threadIdx.x & 31) == 0) need[bh * 8 + c] = any | (c == 7);
}

// produce flags for G4x blocks: (b, chunk, nblock of 2 heads); dilate back 1 chunk
__global__ void pflag_kernel(const int* __restrict__ need, int* __restrict__ pflag)
{
    int b = blockIdx.x;
    int tid = threadIdx.x;
    int c = tid >> 3, nb = tid & 7;
    int h0 = nb * 2, h1 = nb * 2 + 1;
    int p = need[(b * 16 + h0) * 8 + c] | need[(b * 16 + h1) * 8 + c];
    if (c < 7)
        p |= need[(b * 16 + h0) * 8 + c + 1] | need[(b * 16 + h1) * 8 + c + 1];
    pflag[(b * 8 + c) * 8 + nb] = p;
}

// ---------------- z GEMV -------------------------------------------------------
__global__ void zv_kernel(const uint32_t* __restrict__ uh,
                          const float* __restrict__ Win,
                          float* __restrict__ zb)
{
    int b  = blockIdx.y;
    int n  = blockIdx.x * 128 + threadIdx.x;
    __shared__ float us[DM];
    const uint32_t* urow = uh + (size_t)(b * L_ + L_ - 1) * 256;
    for (int i = threadIdx.x; i < 256; i += 128) {
        __half2 h = *(const __half2*)&urow[i];
        float2 f = __half22float2(h);
        us[2 * i] = f.x; us[2 * i + 1] = f.y;
    }
    __syncthreads();
    float acc = 0.f;
    #pragma unroll 8
    for (int d = 0; d < DM; d++) acc = fmaf(us[d], Win[(size_t)d * DPROJ + n], acc);
    zb[b * DI + n] = acc;
}

// ---------------- fused conv-x + time reduction (chunk-skipping) ----------------
__global__ void xy_kernel(const float* __restrict__ xbcr,
                          const float* __restrict__ conv_w,
                          const float* __restrict__ conv_b,
                          const float* __restrict__ wbuf,
                          const int* __restrict__ need,
                          const float* __restrict__ D,
                          float* __restrict__ y)
{
    int bh = blockIdx.x;
    int b = bh >> 4, h = bh & (H_ - 1);
    int tid = threadIdx.x;                // 512 threads: 8 tq x 64 p
    int tq = tid >> 6;
    int p  = tid & 63;
    int c  = h * P_ + p;

    __shared__ float w[L_];
    __shared__ float partial[8][64];

    const float* wrow = wbuf + (size_t)bh * L_;
    for (int i = tid; i < L_; i += 512) w[i] = wrow[i];
    __syncthreads();

    float acc = 0.f;
    if (need[bh * 8 + tq]) {
        float w0 = conv_w[c * 4 + 0], w1 = conv_w[c * 4 + 1];
        float w2 = conv_w[c * 4 + 2], w3 = conv_w[c * 4 + 3];
        float cb = conv_b[c];
        const float* col = xbcr + (size_t)b * L_ * REST + c;
        const int t0 = tq * 128;
        float xm3 = (t0 - 3 >= 0) ? col[(size_t)(t0 - 3) * REST] : 0.f;
        float xm2 = (t0 - 2 >= 0) ? col[(size_t)(t0 - 2) * REST] : 0.f;
        float xm1 = (t0 - 1 >= 0) ? col[(size_t)(t0 - 1) * REST] : 0.f;
        float vlast = 0.f;
        for (int j = 0; j < 128; j += 8) {
            float xv[8];
            #pragma unroll
            for (int i = 0; i < 8; i++)
                xv[i] = col[(size_t)(t0 + j + i) * REST];
            #pragma unroll
            for (int i = 0; i < 8; i++) {
                float v = siluf(fmaf(w0, xm3, fmaf(w1, xm2, fmaf(w2, xm1, fmaf(w3, xv[i], cb)))));
                acc = fmaf(w[t0 + j + i], v, acc);
                vlast = v;
                xm3 = xm2; xm2 = xm1; xm1 = xv[i];
            }
        }
        if (tq == 7) acc = fmaf(D[h], vlast, acc);
    }
    partial[tq][p] = acc;
    __syncthreads();
    if (tq == 0) {
        float s = 0.f;
        #pragma unroll
        for (int qi = 0; qi < 8; qi++) s += partial[qi][p];
        y[bh * P_ + p] = s;
    }
}

// ---------------- gate + rmsnorm + Wout + Wc head ------------------------------
__global__ void final_kernel(const float* __restrict__ y,
                             const float* __restrict__ zlast,
                             const float* __restrict__ norm_w,
                             const float* __restrict__ Wout,
                             const float* __restrict__ Wc,
                             const float* __restrict__ bc,
                             float* __restrict__ out)
{
    int b = blockIdx.x;
    int tid = threadIdx.x;
    __shared__ float yn[DI];
    __shared__ float seq[DM];
    __shared__ float red[256];
    float ss = 0.f;
    for (int d = tid; d < DI; d += 256) {
        float z = zlast[b * DI + d];
        float g = y[b * DI + d] * (z / (1.f + __expf(-z)));
        yn[d] = g;
        ss += g * g;
    }
    red[tid] = ss; __syncthreads();
    for (int o = 128; o; o >>= 1) { if (tid < o) red[tid] += red[tid + o]; __syncthreads(); }
    float scale = rsqrtf(red[0] / (float)DI + EPS);
    for (int d = tid; d < DI; d += 256) yn[d] *= scale * norm_w[d];
    __syncthreads();
    for (int m = tid; m < DM; m += 256) {
        float accm = 0.f;
        for (int d = 0; d < DI; d++) accm = fmaf(yn[d], Wout[(size_t)d * DM + m], accm);
        seq[m] = accm;
    }
    __syncthreads();
    if (tid < NCLS) {
        float acc = bc[tid];
        for (int m = 0; m < DM; m++) acc = fmaf(seq[m], Wc[m * NCLS + tid], acc);
        out[b * NCLS + tid] = acc;
    }
}

// ---------------- launch -------------------------------------------------------
extern "C" void kernel_launch(void* const* d_in, const int* in_sizes, int n_in,
                              void* d_out, int out_size)
{
    const float* x       = (const float*)d_in[0];
    const float* W1      = (const float*)d_in[1];
    const float* b1      = (const float*)d_in[2];
    const float* W2      = (const float*)d_in[3];
    const float* b2      = (const float*)d_in[4];
    const float* W3      = (const float*)d_in[5];
    const float* b3      = (const float*)d_in[6];
    const float* Win     = (const float*)d_in[7];
    const float* conv_w  = (const float*)d_in[8];
    const float* conv_b  = (const float*)d_in[9];
    const float* dt_bias = (const float*)d_in[10];
    const float* A_log   = (const float*)d_in[11];
    const float* Dv      = (const float*)d_in[12];
    const float* norm_w  = (const float*)d_in[13];
    const float* Wout    = (const float*)d_in[14];
    const float* Wc      = (const float*)d_in[15];
    const float* bc      = (const float*)d_in[16];
    float* out = (float*)d_out;

    uint32_t *h1h, *h2h, *uh, *w2th, *w3th, *winth;
    float *xbcr, *Bm, *Cm, *dtp, *beta, *wbuf, *yb, *zb;
    int *need, *pflag;
    cudaGetSymbolAddress((void**)&h1h,  g_h1h);
    cudaGetSymbolAddress((void**)&h2h,  g_h2h);
    cudaGetSymbolAddress((void**)&uh,   g_uh);
    cudaGetSymbolAddress((void**)&w2th, g_w2th);
    cudaGetSymbolAddress((void**)&w3th, g_w3th);
    cudaGetSymbolAddress((void**)&winth,g_winth);
    cudaGetSymbolAddress((void**)&xbcr, g_xbcr);
    cudaGetSymbolAddress((void**)&Bm,   g_Bm);
    cudaGetSymbolAddress((void**)&Cm,   g_Cm);
    cudaGetSymbolAddress((void**)&dtp,  g_dtp);
    cudaGetSymbolAddress((void**)&beta, g_beta);
    cudaGetSymbolAddress((void**)&wbuf, g_wbuf);
    cudaGetSymbolAddress((void**)&need, g_need);
    cudaGetSymbolAddress((void**)&pflag,g_pflag);
    cudaGetSymbolAddress((void**)&yb,   g_y);
    cudaGetSymbolAddress((void**)&zb,   g_z);

    static bool attr_done = false;
    if (!attr_done) {
        cudaFuncSetAttribute(hgemm_kernel<1,1>, cudaFuncAttributeMaxDynamicSharedMemorySize, SMEM_BYTES);
        cudaFuncSetAttribute(hgemm_kernel<0,1>, cudaFuncAttributeMaxDynamicSharedMemorySize, SMEM_BYTES);
        cudaFuncSetAttribute(hgemm_kernel<0,0>, cudaFuncAttributeMaxDynamicSharedMemorySize, SMEM_BYTES);
        attr_done = true;
    }

    // weight packing (fp16 pair-major)
    prep_kernel<<<(256 * WPAD + 255) / 256, 256>>>(W2, W3, Win);
    // G1: x -> 128 (fp32 fma, packed-half output)
    sgemm1_kernel<<<dim3(1, BL/128), 256>>>(x, W1, b1, h1h);
    // G2: 128 -> 256
    hgemm_kernel<1, 1><<<dim3(2, BL/128), 256, SMEM_BYTES>>>(
        h1h, 64, w2th, 256, b2, (float*)h2h, 128, 256, 128, 0, nullptr);
    // G3: 256 -> 512
    hgemm_kernel<0, 1><<<dim3(4, BL/128), 256, SMEM_BYTES>>>(
        h2h, 128, w3th, 512, b3, (float*)uh, 256, 512, 256, 0, nullptr);
    // G4a: B/C columns only (n-block 8 = cols 1024..1151)
    hgemm_kernel<0, 0><<<dim3(1, BL/128), 256, SMEM_BYTES>>>(
        uh, 256, winth, WPAD, nullptr, xbcr, REST, REST, 512, 8, nullptr);
    // dt projection directly into dtp (cols 1152..1167, softplus fused)
    dtproj_kernel<<<BL/8, 128>>>(uh, winth, dt_bias, dtp);
    // conv for B/C channels
    conv_kernel<<<dim3(1, B_, L_/LCH), 128>>>(xbcr, conv_w, conv_b, Bm, Cm);
    // beta
    beta_kernel<<<BL/8, 256>>>(Bm, Cm, beta);
    // fused suffix scan + w + need flags
    scanw_kernel<<<B_*H_, 256>>>(dtp, A_log, beta, wbuf, need);
    // produce flags for G4x
    pflag_kernel<<<B_, 64>>>(need, pflag);
    // G4b: x columns (n-blocks 0..7) with block skip
    hgemm_kernel<0, 0><<<dim3(8, BL/128), 256, SMEM_BYTES>>>(
        uh, 256, winth, WPAD, nullptr, xbcr, REST, REST, 512, 0, pflag);
    // z GEMV at last position
    zv_kernel<<<dim3(8, B_), 128>>>(uh, Win, zb);
    // fused conv-x + y reduction with chunk skip
    xy_kernel<<<B_*H_, 512>>>(xbcr, conv_w, conv_b, wbuf, need, Dv, yb);
    // head
    final_kernel<<<B_, 256>>>(yb, zb, norm_w, Wout, Wc, bc, out);
    (void)in_sizes; (void)n_in; (void)out_size;
}

// round 14
// speedup vs baseline: 1.0949x; 1.0949x over previous
#include <cuda_runtime.h>
#include <cuda_fp16.h>
#include <math.h>
#include <stdint.h>

// ---------------- problem constants ----------------
#define B_  32
#define L_  1024
#define DIN 16
#define DM  512
#define DI  1024          // EXP*DM
#define H_  16            // DI/P
#define P_  64
#define N_  64
#define DCONV 4
#define CONV_DIM 1152     // DI + 2N
#define DPROJ 2192        // 2*DI + 2*N + H
#define REST 1168         // CONV_DIM + H
#define NCLS 10
#define BL  (B_*L_)       // 32768
#define EPS 1e-5f

// fragment-ordered weight buffer sizes (words): T * NBLK * 2048
#define W2F_WORDS  (4  * 2  * 2048)
#define W3F_WORDS  (8  * 4  * 2048)
#define WINF_WORDS (16 * 10 * 2048)

// ---------------- scratch (static device globals; no allocations) -------------
__device__ uint32_t g_h1h[BL*64];            // [BL][64]
__device__ uint32_t g_h2h[(size_t)BL*128];   // [BL][128]
__device__ uint32_t g_uh [(size_t)BL*256];   // [BL][256]
// packed half2 weights in staged-fragment order
__device__ uint32_t g_w2f[W2F_WORDS];
__device__ uint32_t g_w3f[W3F_WORDS];
__device__ uint32_t g_winf[WINF_WORDS];
// fp32 intermediates
__device__ float g_xbcr[(size_t)BL*REST];
__device__ float g_Bm [BL*N_];
__device__ float g_Cm [B_*N_];
__device__ float g_dtp[B_*H_*L_];
__device__ float g_coef[B_*H_*L_];
__device__ float g_beta[BL];
__device__ float g_wbuf[B_*H_*L_];           // w = coef*beta
__device__ int   g_need [B_*H_*8];           // per (bh, chunk) compute flag
__device__ int   g_pflag[B_*8*8];            // per (b, chunk, nblock) produce flag
__device__ float g_y  [B_*DI];
__device__ float g_z  [B_*DI];

// ---------------- helpers ------------------------------------------------------
__device__ __forceinline__ uint32_t pack_h2(float a, float b) {
    __half2 h = __floats2half2_rn(a, b);
    return *(uint32_t*)&h;
}
__device__ __forceinline__ void mma_f16(float* c, const uint32_t* a, const uint32_t* b) {
    asm volatile(
        "mma.sync.aligned.m16n8k16.row.col.f32.f16.f16.f32 "
        "{%0,%1,%2,%3}, {%4,%5,%6,%7}, {%8,%9}, {%0,%1,%2,%3};\n"
        : "+f"(c[0]), "+f"(c[1]), "+f"(c[2]), "+f"(c[3])
        : "r"(a[0]), "r"(a[1]), "r"(a[2]), "r"(a[3]), "r"(b[0]), "r"(b[1]));
}
__device__ __forceinline__ void ldmx4(uint32_t& r0, uint32_t& r1, uint32_t& r2, uint32_t& r3,
                                      uint32_t saddr) {
    asm volatile("ldmatrix.sync.aligned.m8n8.x4.shared.b16 {%0,%1,%2,%3}, [%4];"
                 : "=r"(r0), "=r"(r1), "=r"(r2), "=r"(r3) : "r"(saddr));
}
__device__ __forceinline__ void cp16(uint32_t saddr, const void* g) {
    asm volatile("cp.async.cg.shared.global [%0], [%1], 16;\n" :: "r"(saddr), "l"(g));
}
__device__ __forceinline__ void cp_commit() { asm volatile("cp.async.commit_group;\n"); }
template<int n> __device__ __forceinline__ void cp_wait() {
    asm volatile("cp.async.wait_group %0;\n" :: "n"(n));
}
__device__ __forceinline__ uint32_t smem_u32(const void* p) {
    uint32_t a;
    asm("{ .reg .u64 t; cvta.to.shared.u64 t, %1; cvt.u32.u64 %0, t; }" : "=r"(a) : "l"(p));
    return a;
}

#define STG 4
#define AW 2048                    // A stage words (128 rows x 16 pair-words)
#define BW 2048                    // B stage words (fragment-ordered, linear)
#define SMEM_BYTES (STG * (AW + BW) * 4)   // 65536

// =============================================================================
// FP16 tensor-core GEMM (m16n8k16, fp32 accum), cp.async 4-stage pipeline.
// A: [M][Kh/2] packed half2 words, lda in words. XOR-swizzled smem + ldmatrix.
// Wf: fragment-ordered weights: word index =
//     ((t*NBLK + nblk)*2048) + ks*1024 + n*8 + lr*2 + sub
//   where value = half2 of k-halves 2p,2p+1 with pair-row p = t*16+ks*8+lr+sub*4,
//   column = nblk*128 + n (OOB columns zero-padded in prep).
//   Staged as a LINEAR 8KB copy; consumed with conflict-free LDS.64:
//   64-bit unit index = ks*512 + (warp_n + ni*8)*4 + lane.
// C: fp32 [M][ldc] if OUTH==0 (n<N guard), else packed half2 [M][ldc].
// bn0 = n-block offset; pflag = optional per-(b,chunk,nblock) CTA skip mask.
// =============================================================================
template<int RELU, int OUTH>
__global__ __launch_bounds__(256, 2) void hgemm_kernel(
    const uint32_t* __restrict__ A, int lda,
    const uint32_t* __restrict__ Wf, int NBLK,
    const float* __restrict__ bias,
    float* __restrict__ C, int ldc,
    int N, int Kh, int bn0, const int* __restrict__ pflag)
{
    if (pflag) {
        int b = blockIdx.y >> 3, chunk = blockIdx.y & 7;
        if (!pflag[(b * 8 + chunk) * 8 + blockIdx.x]) return;
    }
    extern __shared__ uint32_t smem[];
    uint32_t* Asm = smem;
    uint32_t* Bsm = smem + STG * AW;

    const int bm = blockIdx.y * 128;
    const int nblk = blockIdx.x + bn0;
    const int bn = nblk * 128;
    const int tid = threadIdx.x;
    const int warp = tid >> 5;
    const int lane = tid & 31;
    const int warp_m = (warp & 1) * 64;
    const int warp_n = (warp >> 1) * 32;
    const int lg = lane >> 2;
    const int lr = lane & 3;

    // A staging coords
    const int am0 = tid >> 2;
    const int akq = tid & 3;
    const int aw0 = am0 * 16 + ((akq ^ (am0 & 3)) << 2);
    const int am1 = am0 + 64;
    const int aw1 = am1 * 16 + ((akq ^ (am1 & 3)) << 2);

    // ldmatrix addressing for A
    const int q  = lane >> 3;
    const int rr = lane & 7;
    const int mlo = rr + (q & 1) * 8;
    const int qh = q >> 1;
    uint32_t asw[4][2];
    #pragma unroll
    for (int mi = 0; mi < 4; mi++) {
        int m = warp_m + mi * 16 + mlo;
        #pragma unroll
        for (int ks = 0; ks < 2; ks++)
            asw[mi][ks] = m * 16 + (((ks * 2 + qh) ^ (m & 3)) << 2);
    }
    const uint32_t as_base = smem_u32(Asm);
    const uint32_t bs_base = smem_u32(Bsm);

    float acc[4][4][4];
    #pragma unroll
    for (int i = 0; i < 4; i++)
        #pragma unroll
        for (int j = 0; j < 4; j++)
            #pragma unroll
            for (int r = 0; r < 4; r++) acc[i][j][r] = 0.f;

    const int T = Kh >> 5;

    auto issue = [&](int t, int s) {
        const int k0 = t * 16;
        cp16(as_base + (s * AW + aw0) * 4, &A[(size_t)(bm + am0) * lda + k0 + akq * 4]);
        cp16(as_base + (s * AW + aw1) * 4, &A[(size_t)(bm + am1) * lda + k0 + akq * 4]);
        const uint32_t* wsrc = Wf + (size_t)(t * NBLK + nblk) * 2048;
        cp16(bs_base + (s * BW + tid * 4) * 4,          &wsrc[tid * 4]);
        cp16(bs_base + (s * BW + (tid + 256) * 4) * 4,  &wsrc[(tid + 256) * 4]);
        cp_commit();
    };

    #pragma unroll
    for (int i = 0; i < STG - 1; i++)
        if (i < T) issue(i, i);

    for (int t = 0; t < T; t++) {
        cp_wait<STG - 2>();
        __syncthreads();
        const int s = t & (STG - 1);
        const uint32_t* Bst = Bsm + s * BW;

        #pragma unroll
        for (int ks = 0; ks < 2; ks++) {
            uint32_t af[4][4], bf[4][2];
            #pragma unroll
            for (int mi = 0; mi < 4; mi++)
                ldmx4(af[mi][0], af[mi][1], af[mi][2], af[mi][3],
                      as_base + (s * AW + asw[mi][ks]) * 4);
            #pragma unroll
            for (int ni = 0; ni < 4; ni++) {
                uint2 bv = *(const uint2*)&Bst[ks * 1024 + (warp_n + ni * 8) * 8 + lane * 2];
                bf[ni][0] = bv.x; bf[ni][1] = bv.y;
            }
            #pragma unroll
            for (int mi = 0; mi < 4; mi++)
                #pragma unroll
                for (int ni = 0; ni < 4; ni++)
                    mma_f16(acc[mi][ni], af[mi], bf[ni]);
        }

        if (t + STG - 1 < T) issue(t + STG - 1, (t + STG - 1) & (STG - 1));
    }

    #pragma unroll
    for (int mi = 0; mi < 4; mi++) {
        #pragma unroll
        for (int half = 0; half < 2; half++) {
            const int gr = bm + warp_m + mi * 16 + lg + half * 8;
            #pragma unroll
            for (int ni = 0; ni < 4; ni++) {
                const int gn = bn + warp_n + ni * 8 + lr * 2;
                float v0 = acc[mi][ni][half * 2 + 0];
                float v1 = acc[mi][ni][half * 2 + 1];
                if (bias) { v0 += bias[gn]; v1 += bias[gn + 1]; }
                if (RELU) { v0 = fmaxf(v0, 0.f); v1 = fmaxf(v1, 0.f); }
                if (OUTH) {
                    ((uint32_t*)C)[(size_t)gr * ldc + (gn >> 1)] = pack_h2(v0, v1);
                } else {
                    if (gn >= N) continue;
                    *(float2*)&C[(size_t)gr * ldc + gn] = make_float2(v0, v1);
                }
            }
        }
    }
}

// ---------------- weight prep: fragment-ordered packing ------------------------
// word i of a buffer: within = i%2048, blk = (i/2048)%NBLK, t = i/(2048*NBLK)
//   ks = within>>10, n = (within>>3)&127, lr = (within&7)>>1, sub = within&1
//   pair-row p = t*16 + ks*8 + lr + sub*4; k = 2p; column = blk*128 + n
__global__ void prep_kernel(const float* __restrict__ W2,
                            const float* __restrict__ W3,
                            const float* __restrict__ Win)
{
    int i = blockIdx.x * 256 + threadIdx.x;
    if (i < W2F_WORDS) {
        int within = i & 2047, blk = (i >> 11) & 1, t = i >> 12;
        int ks = within >> 10, n = (within >> 3) & 127;
        int lr = (within & 7) >> 1, sub = within & 1;
        int k = 2 * (t * 16 + ks * 8 + lr + sub * 4);
        int col = blk * 128 + n;
        g_w2f[i] = pack_h2(W2[k * 256 + col], W2[(k + 1) * 256 + col]);
    }
    if (i < W3F_WORDS) {
        int within = i & 2047, blk = (i >> 11) & 3, t = i >> 13;
        int ks = within >> 10, n = (within >> 3) & 127;
        int lr = (within & 7) >> 1, sub = within & 1;
        int k = 2 * (t * 16 + ks * 8 + lr + sub * 4);
        int col = blk * 128 + n;
        g_w3f[i] = pack_h2(W3[k * 512 + col], W3[(k + 1) * 512 + col]);
    }
    if (i < WINF_WORDS) {
        int within = i & 2047, blk = (i >> 11) % 10, t = i / (2048 * 10);
        int ks = within >> 10, n = (within >> 3) & 127;
        int lr = (within & 7) >> 1, sub = within & 1;
        int k = 2 * (t * 16 + ks * 8 + lr + sub * 4);
        int col = blk * 128 + n;
        g_winf[i] = (col < REST)
            ? pack_h2(Win[(size_t)k * DPROJ + DI + col],
                      Win[(size_t)(k + 1) * DPROJ + DI + col])
            : 0u;
    }
}

// ---------------- G1: fp32 fma SGEMM, packed-half output -----------------------
__global__ void sgemm1_kernel(const float* __restrict__ A,
                              const float* __restrict__ W,
                              const float* __restrict__ bias,
                              uint32_t* __restrict__ Ch)
{
    __shared__ float As[8][128];
    __shared__ float Bs[8][128];
    const int bm = blockIdx.y * 128;
    const int tid = threadIdx.x;
    const int tr = tid >> 4;
    const int tc = tid & 15;

    float acc[8][8];
    #pragma unroll
    for (int i = 0; i < 8; i++)
        #pragma unroll
        for (int j = 0; j < 8; j++) acc[i][j] = 0.f;

    for (int k0 = 0; k0 < DIN; k0 += 8) {
        {
            int e = tid * 4;
            int r = e >> 3, kk = e & 7;
            float4 av = *(const float4*)&A[(size_t)(bm + r) * DIN + k0 + kk];
            As[kk + 0][r] = av.x; As[kk + 1][r] = av.y;
            As[kk + 2][r] = av.z; As[kk + 3][r] = av.w;
        }
        {
            int e = tid * 4;
            int kk = e >> 7, n = e & 127;
            const float* wrow = W + (size_t)(k0 + kk) * 128;
            #pragma unroll
            for (int i = 0; i < 4; i++) Bs[kk][n + i] = wrow[n + i];
        }
        __syncthreads();
        #pragma unroll
        for (int kk = 0; kk < 8; kk++) {
            float4 a0 = *(const float4*)&As[kk][tr * 4];
            float4 a1 = *(const float4*)&As[kk][64 + tr * 4];
            float4 b0 = *(const float4*)&Bs[kk][tc * 4];
            float4 b1 = *(const float4*)&Bs[kk][64 + tc * 4];
            float a[8] = {a0.x,a0.y,a0.z,a0.w,a1.x,a1.y,a1.z,a1.w};
            float b[8] = {b0.x,b0.y,b0.z,b0.w,b1.x,b1.y,b1.z,b1.w};
            #pragma unroll
            for (int i = 0; i < 8; i++)
                #pragma unroll
                for (int j = 0; j < 8; j++) acc[i][j] = fmaf(a[i], b[j], acc[i][j]);
        }
        __syncthreads();
    }
    #pragma unroll
    for (int i = 0; i < 8; i++) {
        int gr = bm + ((i < 4) ? (tr * 4 + i) : (64 + tr * 4 + i - 4));
        #pragma unroll
        for (int j = 0; j < 8; j += 2) {
            int gn = (j < 4) ? (tc * 4 + j) : (64 + tc * 4 + j - 4);
            float v0 = fmaxf(acc[i][j]     + bias[gn],     0.f);
            float v1 = fmaxf(acc[i][j + 1] + bias[gn + 1], 0.f);
            Ch[(size_t)gr * 64 + (gn >> 1)] = pack_h2(v0, v1);
        }
    }
}

// ---------------- activation helpers ------------------------------------------
__device__ __forceinline__ float siluf(float x) { return x / (1.f + __expf(-x)); }
__device__ __forceinline__ float softplusf(float x) {
    return (x > 0.f) ? x + log1pf(__expf(-x)) : log1pf(__expf(x));
}

// ---------------- conv for B/C/dt channels (144 channels) ----------------------
#define LCH 128
__global__ void conv_kernel(const float* __restrict__ xbcr,
                            const float* __restrict__ conv_w,
                            const float* __restrict__ conv_b,
                            const float* __restrict__ dt_bias,
                            float* __restrict__ Bm,
                            float* __restrict__ Cm, float* __restrict__ dtp)
{
    int c  = DI + threadIdx.x;
    int b  = blockIdx.y;
    int l0 = blockIdx.z * LCH;
    if (c >= REST) return;
    const float* col = xbcr + (size_t)b * L_ * REST + c;

    if (c >= CONV_DIM) {
        int h = c - CONV_DIM;
        float bias = dt_bias[h];
        float* drow = dtp + (size_t)(b * H_ + h) * L_;
        #pragma unroll 4
        for (int l = l0; l < l0 + LCH; l++)
            drow[l] = softplusf(col[(size_t)l * REST] + bias);
        return;
    }
    float w0 = conv_w[c * 4 + 0], w1 = conv_w[c * 4 + 1];
    float w2 = conv_w[c * 4 + 2], w3 = conv_w[c * 4 + 3];
    float cb = conv_b[c];

    if (c >= DI + N_) {
        if (l0 + LCH != L_) return;
        int l = L_ - 1;
        float acc = cb + w0 * col[(size_t)(l - 3) * REST] + w1 * col[(size_t)(l - 2) * REST]
                       + w2 * col[(size_t)(l - 1) * REST] + w3 * col[(size_t)l * REST];
        Cm[b * N_ + (c - DI - N_)] = siluf(acc);
        return;
    }
    float xm3 = (l0 - 3 >= 0) ? col[(size_t)(l0 - 3) * REST] : 0.f;
    float xm2 = (l0 - 2 >= 0) ? col[(size_t)(l0 - 2) * REST] : 0.f;
    float xm1 = (l0 - 1 >= 0) ? col[(size_t)(l0 - 1) * REST] : 0.f;
    float* orow = Bm + (size_t)(b * L_ + l0) * N_ + (c - DI);
    #pragma unroll 4
    for (int l = l0; l < l0 + LCH; l++) {
        float xl = col[(size_t)l * REST];
        float acc = fmaf(w0, xm3, fmaf(w1, xm2, fmaf(w2, xm1, fmaf(w3, xl, cb))));
        *orow = siluf(acc);
        orow += N_;
        xm3 = xm2; xm2 = xm1; xm1 = xl;
    }
}

// ---------------- suffix-sum of dt and coefficient exp(-a*S)*dt ----------------
__global__ void scan_kernel(const float* __restrict__ dtp,
                            const float* __restrict__ A_log,
                            float* __restrict__ coef)
{
    int bh = blockIdx.x;
    int h = bh & (H_ - 1);
    float a = expf(A_log[h]);
    __shared__ float part[256];
    __shared__ float off[256];
    const float* row = dtp + (size_t)bh * L_;
    int t0 = threadIdx.x * 4;
    float v0 = row[t0], v1 = row[t0 + 1], v2 = row[t0 + 2], v3 = row[t0 + 3];
    part[threadIdx.x] = v0 + v1 + v2 + v3;
    __syncthreads();
    if (threadIdx.x == 0) {
        float s = 0.f;
        for (int i = 255; i >= 0; i--) { off[i] = s; s += part[i]; }
    }
    __syncthreads();
    float S3 = off[threadIdx.x];
    float S2 = S3 + v3;
    float S1 = S2 + v2;
    float S0 = S1 + v1;
    float* out = coef + (size_t)bh * L_;
    out[t0 + 0] = expf(-a * S0) * v0;
    out[t0 + 1] = expf(-a * S1) * v1;
    out[t0 + 2] = expf(-a * S2) * v2;
    out[t0 + 3] = expf(-a * S3) * v3;
}

// ---------------- beta[b,t] = B_t . C_last -------------------------------------
__global__ void beta_kernel(const float* __restrict__ Bm,
                            const float* __restrict__ Cm,
                            float* __restrict__ beta)
{
    int row = blockIdx.x * 8 + (threadIdx.x >> 5);
    int b = row >> 10;
    int lane = threadIdx.x & 31;
    float s = Bm[(size_t)row * N_ + lane]      * Cm[b * N_ + lane]
            + Bm[(size_t)row * N_ + 32 + lane] * Cm[b * N_ + 32 + lane];
    #pragma unroll
    for (int o = 16; o; o >>= 1) s += __shfl_down_sync(0xffffffffu, s, o);
    if (lane == 0) beta[row] = s;
}

// ---------------- w = coef*beta + per-chunk nonzero flags ----------------------
__global__ void wflag_kernel(const float* __restrict__ coef,
                             const float* __restrict__ beta,
                             float* __restrict__ wbuf,
                             int* __restrict__ need)
{
    int bh = blockIdx.x;
    int b = bh >> 4;
    int tid = threadIdx.x;
    const float* crow = coef + (size_t)bh * L_;
    const float* brow = beta + (size_t)b * L_;
    float* wrow = wbuf + (size_t)bh * L_;
    for (int c = 0; c < 8; c++) {
        int t = c * 128 + tid;
        float wv = crow[t] * brow[t];
        wrow[t] = wv;
        int any = __syncthreads_or(wv != 0.f);
        if (tid == 0) need[bh * 8 + c] = any | (c == 7 ? 1 : 0);
    }
}

// produce flags for G4x blocks
__global__ void pflag_kernel(const int* __restrict__ need, int* __restrict__ pflag)
{
    int b = blockIdx.x;
    int tid = threadIdx.x;
    int c = tid >> 3, nb = tid & 7;
    int h0 = nb * 2, h1 = nb * 2 + 1;
    int p = need[(b * 16 + h0) * 8 + c] | need[(b * 16 + h1) * 8 + c];
    if (c < 7)
        p |= need[(b * 16 + h0) * 8 + c + 1] | need[(b * 16 + h1) * 8 + c + 1];
    pflag[(b * 8 + c) * 8 + nb] = p;
}

// ---------------- z GEMV -------------------------------------------------------
__global__ void zv_kernel(const uint32_t* __restrict__ uh,
                          const float* __restrict__ Win,
                          float* __restrict__ zb)
{
    int b  = blockIdx.y;
    int n  = blockIdx.x * 128 + threadIdx.x;
    __shared__ float us[DM];
    const uint32_t* urow = uh + (size_t)(b * L_ + L_ - 1) * 256;
    for (int i = threadIdx.x; i < 256; i += 128) {
        __half2 h = *(const __half2*)&urow[i];
        float2 f = __half22float2(h);
        us[2 * i] = f.x; us[2 * i + 1] = f.y;
    }
    __syncthreads();
    float acc = 0.f;
    #pragma unroll 8
    for (int d = 0; d < DM; d++) acc = fmaf(us[d], Win[(size_t)d * DPROJ + n], acc);
    zb[b * DI + n] = acc;
}

// ---------------- fused conv-x + time reduction (chunk-skipping) ----------------
__global__ void xy_kernel(const float* __restrict__ xbcr,
                          const float* __restrict__ conv_w,
                          const float* __restrict__ conv_b,
                          const float* __restrict__ wbuf,
                          const int* __restrict__ need,
                          const float* __restrict__ D,
                          float* __restrict__ y)
{
    int bh = blockIdx.x;
    int b = bh >> 4, h = bh & (H_ - 1);
    int tid = threadIdx.x;
    int tq = tid >> 6;
    int p  = tid & 63;
    int c  = h * P_ + p;

    __shared__ float w[L_];
    __shared__ float partial[8][64];

    const float* wrow = wbuf + (size_t)bh * L_;
    for (int i = tid; i < L_; i += 512) w[i] = wrow[i];
    __syncthreads();

    float acc = 0.f;
    if (need[bh * 8 + tq]) {
        float w0 = conv_w[c * 4 + 0], w1 = conv_w[c * 4 + 1];
        float w2 = conv_w[c * 4 + 2], w3 = conv_w[c * 4 + 3];
        float cb = conv_b[c];
        const float* col = xbcr + (size_t)b * L_ * REST + c;
        const int t0 = tq * 128;
        float xm3 = (t0 - 3 >= 0) ? col[(size_t)(t0 - 3) * REST] : 0.f;
        float xm2 = (t0 - 2 >= 0) ? col[(size_t)(t0 - 2) * REST] : 0.f;
        float xm1 = (t0 - 1 >= 0) ? col[(size_t)(t0 - 1) * REST] : 0.f;
        float vlast = 0.f;
        for (int j = 0; j < 128; j += 8) {
            float xv[8];
            #pragma unroll
            for (int i = 0; i < 8; i++)
                xv[i] = col[(size_t)(t0 + j + i) * REST];
            #pragma unroll
            for (int i = 0; i < 8; i++) {
                float v = siluf(fmaf(w0, xm3, fmaf(w1, xm2, fmaf(w2, xm1, fmaf(w3, xv[i], cb)))));
                acc = fmaf(w[t0 + j + i], v, acc);
                vlast = v;
                xm3 = xm2; xm2 = xm1; xm1 = xv[i];
            }
        }
        if (tq == 7) acc = fmaf(D[h], vlast, acc);
    }
    partial[tq][p] = acc;
    __syncthreads();
    if (tq == 0) {
        float s = 0.f;
        #pragma unroll
        for (int qi = 0; qi < 8; qi++) s += partial[qi][p];
        y[bh * P_ + p] = s;
    }
}

// ---------------- gate + rmsnorm + Wout + Wc head ------------------------------
__global__ void final_kernel(const float* __restrict__ y,
                             const float* __restrict__ zlast,
                             const float* __restrict__ norm_w,
                             const float* __restrict__ Wout,
                             const float* __restrict__ Wc,
                             const float* __restrict__ bc,
                             float* __restrict__ out)
{
    int b = blockIdx.x;
    int tid = threadIdx.x;
    __shared__ float yn[DI];
    __shared__ float seq[DM];
    __shared__ float red[256];
    float ss = 0.f;
    for (int d = tid; d < DI; d += 256) {
        float z = zlast[b * DI + d];
        float g = y[b * DI + d] * (z / (1.f + __expf(-z)));
        yn[d] = g;
        ss += g * g;
    }
    red[tid] = ss; __syncthreads();
    for (int o = 128; o; o >>= 1) { if (tid < o) red[tid] += red[tid + o]; __syncthreads(); }
    float scale = rsqrtf(red[0] / (float)DI + EPS);
    for (int d = tid; d < DI; d += 256) yn[d] *= scale * norm_w[d];
    __syncthreads();
    for (int m = tid; m < DM; m += 256) {
        float accm = 0.f;
        for (int d = 0; d < DI; d++) accm = fmaf(yn[d], Wout[(size_t)d * DM + m], accm);
        seq[m] = accm;
    }
    __syncthreads();
    if (tid < NCLS) {
        float acc = bc[tid];
        for (int m = 0; m < DM; m++) acc = fmaf(seq[m], Wc[m * NCLS + tid], acc);
        out[b * NCLS + tid] = acc;
    }
}

// ---------------- launch -------------------------------------------------------
extern "C" void kernel_launch(void* const* d_in, const int* in_sizes, int n_in,
                              void* d_out, int out_size)
{
    const float* x       = (const float*)d_in[0];
    const float* W1      = (const float*)d_in[1];
    const float* b1      = (const float*)d_in[2];
    const float* W2      = (const float*)d_in[3];
    const float* b2      = (const float*)d_in[4];
    const float* W3      = (const float*)d_in[5];
    const float* b3      = (const float*)d_in[6];
    const float* Win     = (const float*)d_in[7];
    const float* conv_w  = (const float*)d_in[8];
    const float* conv_b  = (const float*)d_in[9];
    const float* dt_bias = (const float*)d_in[10];
    const float* A_log   = (const float*)d_in[11];
    const float* Dv      = (const float*)d_in[12];
    const float* norm_w  = (const float*)d_in[13];
    const float* Wout    = (const float*)d_in[14];
    const float* Wc      = (const float*)d_in[15];
    const float* bc      = (const float*)d_in[16];
    float* out = (float*)d_out;

    uint32_t *h1h, *h2h, *uh, *w2f, *w3f, *winf;
    float *xbcr, *Bm, *Cm, *dtp, *coef, *beta, *wbuf, *yb, *zb;
    int *need, *pflag;
    cudaGetSymbolAddress((void**)&h1h,  g_h1h);
    cudaGetSymbolAddress((void**)&h2h,  g_h2h);
    cudaGetSymbolAddress((void**)&uh,   g_uh);
    cudaGetSymbolAddress((void**)&w2f,  g_w2f);
    cudaGetSymbolAddress((void**)&w3f,  g_w3f);
    cudaGetSymbolAddress((void**)&winf, g_winf);
    cudaGetSymbolAddress((void**)&xbcr, g_xbcr);
    cudaGetSymbolAddress((void**)&Bm,   g_Bm);
    cudaGetSymbolAddress((void**)&Cm,   g_Cm);
    cudaGetSymbolAddress((void**)&dtp,  g_dtp);
    cudaGetSymbolAddress((void**)&coef, g_coef);
    cudaGetSymbolAddress((void**)&beta, g_beta);
    cudaGetSymbolAddress((void**)&wbuf, g_wbuf);
    cudaGetSymbolAddress((void**)&need, g_need);
    cudaGetSymbolAddress((void**)&pflag,g_pflag);
    cudaGetSymbolAddress((void**)&yb,   g_y);
    cudaGetSymbolAddress((void**)&zb,   g_z);

    static bool attr_done = false;
    if (!attr_done) {
        cudaFuncSetAttribute(hgemm_kernel<1,1>, cudaFuncAttributeMaxDynamicSharedMemorySize, SMEM_BYTES);
        cudaFuncSetAttribute(hgemm_kernel<0,1>, cudaFuncAttributeMaxDynamicSharedMemorySize, SMEM_BYTES);
        cudaFuncSetAttribute(hgemm_kernel<0,0>, cudaFuncAttributeMaxDynamicSharedMemorySize, SMEM_BYTES);
        attr_done = true;
    }

    // weight packing (fragment-ordered fp16)
    prep_kernel<<<(WINF_WORDS + 255) / 256, 256>>>(W2, W3, Win);
    // G1: x -> 128 (fp32 fma, packed-half output)
    sgemm1_kernel<<<dim3(1, BL/128), 256>>>(x, W1, b1, h1h);
    // G2: 128 -> 256 (NBLK=2)
    hgemm_kernel<1, 1><<<dim3(2, BL/128), 256, SMEM_BYTES>>>(
        h1h, 64, w2f, 2, b2, (float*)h2h, 128, 256, 128, 0, nullptr);
    // G3: 256 -> 512 (NBLK=4)
    hgemm_kernel<0, 1><<<dim3(4, BL/128), 256, SMEM_BYTES>>>(
        h2h, 128, w3f, 4, b3, (float*)uh, 256, 512, 256, 0, nullptr);
    // G4a: B/C/dt columns (n-blocks 8..9, NBLK=10)
    hgemm_kernel<0, 0><<<dim3(2, BL/128), 256, SMEM_BYTES>>>(
        uh, 256, winf, 10, nullptr, xbcr, REST, REST, 512, 8, nullptr);
    // conv for B/C/dt channels
    conv_kernel<<<dim3(1, B_, L_/LCH), 192>>>(xbcr, conv_w, conv_b, dt_bias, Bm, Cm, dtp);
    // suffix scan -> coef
    scan_kernel<<<B_*H_, 256>>>(dtp, A_log, coef);
    // beta
    beta_kernel<<<BL/8, 256>>>(Bm, Cm, beta);
    // w = coef*beta + need flags
    wflag_kernel<<<B_*H_, 128>>>(coef, beta, wbuf, need);
    // produce flags for G4x
    pflag_kernel<<<B_, 64>>>(need, pflag);
    // G4b: x columns (n-blocks 0..7) with block skip
    hgemm_kernel<0, 0><<<dim3(8, BL/128), 256, SMEM_BYTES>>>(
        uh, 256, winf, 10, nullptr, xbcr, REST, REST, 512, 0, pflag);
    // z GEMV at last position
    zv_kernel<<<dim3(8, B_), 128>>>(uh, Win, zb);
    // fused conv-x + y reduction with chunk skip
    xy_kernel<<<B_*H_, 512>>>(xbcr, conv_w, conv_b, wbuf, need, Dv, yb);
    // head
    final_kernel<<<B_, 256>>>(yb, zb, norm_w, Wout, Wc, bc, out);
    (void)in_sizes; (void)n_in; (void)out_size;
}

// round 15
// speedup vs baseline: 1.1414x; 1.0425x over previous
#include <cuda_runtime.h>
#include <cuda_fp16.h>
#include <math.h>
#include <stdint.h>

// ---------------- problem constants ----------------
#define B_  32
#define L_  1024
#define DIN 16
#define DM  512
#define DI  1024          // EXP*DM
#define H_  16            // DI/P
#define P_  64
#define N_  64
#define DCONV 4
#define CONV_DIM 1152     // DI + 2N
#define DPROJ 2192        // 2*DI + 2*N + H
#define REST 1168         // CONV_DIM + H
#define NCLS 10
#define BL  (B_*L_)       // 32768
#define EPS 1e-5f

// fragment-ordered weight buffer sizes (words): T * NBLK * 2048
#define W2F_WORDS  (4  * 2  * 2048)
#define W3F_WORDS  (8  * 4  * 2048)
#define WINF_WORDS (16 * 10 * 2048)

// ---------------- scratch (static device globals; no allocations) -------------
__device__ uint32_t g_h1h[BL*64];            // [BL][64]
__device__ uint32_t g_h2h[(size_t)BL*128];   // [BL][128]
__device__ uint32_t g_uh [(size_t)BL*256];   // [BL][256]
// packed half2 weights in staged-fragment order
__device__ uint32_t g_w2f[W2F_WORDS];
__device__ uint32_t g_w3f[W3F_WORDS];
__device__ uint32_t g_winf[WINF_WORDS];
// fp32 intermediates
__device__ float g_xbcr[(size_t)BL*REST];
__device__ float g_Bm [BL*N_];
__device__ float g_Cm [B_*N_];
__device__ float g_dtp[B_*H_*L_];
__device__ float g_beta[BL];
__device__ float g_wbuf[B_*H_*L_];           // w = coef*beta
__device__ int   g_need [B_*H_*8];           // per (bh, chunk) compute flag
__device__ int   g_pflag[B_*8*8];            // per (b, chunk, nblock) produce flag
__device__ float g_y  [B_*DI];
__device__ float g_z  [B_*DI];

// ---------------- helpers ------------------------------------------------------
__device__ __forceinline__ uint32_t pack_h2(float a, float b) {
    __half2 h = __floats2half2_rn(a, b);
    return *(uint32_t*)&h;
}
__device__ __forceinline__ void mma_f16(float* c, const uint32_t* a, const uint32_t* b) {
    asm volatile(
        "mma.sync.aligned.m16n8k16.row.col.f32.f16.f16.f32 "
        "{%0,%1,%2,%3}, {%4,%5,%6,%7}, {%8,%9}, {%0,%1,%2,%3};\n"
        : "+f"(c[0]), "+f"(c[1]), "+f"(c[2]), "+f"(c[3])
        : "r"(a[0]), "r"(a[1]), "r"(a[2]), "r"(a[3]), "r"(b[0]), "r"(b[1]));
}
__device__ __forceinline__ void ldmx4(uint32_t& r0, uint32_t& r1, uint32_t& r2, uint32_t& r3,
                                      uint32_t saddr) {
    asm volatile("ldmatrix.sync.aligned.m8n8.x4.shared.b16 {%0,%1,%2,%3}, [%4];"
                 : "=r"(r0), "=r"(r1), "=r"(r2), "=r"(r3) : "r"(saddr));
}
__device__ __forceinline__ void cp16(uint32_t saddr, const void* g) {
    asm volatile("cp.async.cg.shared.global [%0], [%1], 16;\n" :: "r"(saddr), "l"(g));
}
__device__ __forceinline__ void cp_commit() { asm volatile("cp.async.commit_group;\n"); }
template<int n> __device__ __forceinline__ void cp_wait() {
    asm volatile("cp.async.wait_group %0;\n" :: "n"(n));
}
__device__ __forceinline__ uint32_t smem_u32(const void* p) {
    uint32_t a;
    asm("{ .reg .u64 t; cvta.to.shared.u64 t, %1; cvt.u32.u64 %0, t; }" : "=r"(a) : "l"(p));
    return a;
}

#define STG 6
#define AW 2048                    // A stage words (128 rows x 16 pair-words)
#define BW 2048                    // B stage words (fragment-ordered, linear)
#define SMEM_BYTES (STG * (AW + BW) * 4)   // 98304; x2 CTAs = 192KB <= 227KB

// =============================================================================
// FP16 tensor-core GEMM (m16n8k16, fp32 accum), cp.async 6-stage pipeline.
// A: [M][Kh/2] packed half2 words, lda in words. XOR-swizzled smem + ldmatrix.
// Wf: fragment-ordered weights (see prep); staged as a LINEAR 8KB copy and
//     consumed with conflict-free LDS.64.
// Every loop iteration commits exactly one group (real or empty) so
// cp_wait<STG-2> provably guarantees group t completion (committed = STG-1+t).
// C: fp32 [M][ldc] if OUTH==0 (n<N guard), else packed half2 [M][ldc].
// bn0 = n-block offset; pflag = optional per-(b,chunk,nblock) CTA skip mask.
// =============================================================================
template<int RELU, int OUTH>
__global__ __launch_bounds__(256, 2) void hgemm_kernel(
    const uint32_t* __restrict__ A, int lda,
    const uint32_t* __restrict__ Wf, int NBLK,
    const float* __restrict__ bias,
    float* __restrict__ C, int ldc,
    int N, int Kh, int bn0, const int* __restrict__ pflag)
{
    if (pflag) {
        int b = blockIdx.y >> 3, chunk = blockIdx.y & 7;
        if (!pflag[(b * 8 + chunk) * 8 + blockIdx.x]) return;
    }
    extern __shared__ uint32_t smem[];
    uint32_t* Asm = smem;
    uint32_t* Bsm = smem + STG * AW;

    const int bm = blockIdx.y * 128;
    const int nblk = blockIdx.x + bn0;
    const int bn = nblk * 128;
    const int tid = threadIdx.x;
    const int warp = tid >> 5;
    const int lane = tid & 31;
    const int warp_m = (warp & 1) * 64;
    const int warp_n = (warp >> 1) * 32;
    const int lg = lane >> 2;
    const int lr = lane & 3;

    // A staging coords
    const int am0 = tid >> 2;
    const int akq = tid & 3;
    const int aw0 = am0 * 16 + ((akq ^ (am0 & 3)) << 2);
    const int am1 = am0 + 64;
    const int aw1 = am1 * 16 + ((akq ^ (am1 & 3)) << 2);

    // ldmatrix addressing for A
    const int q  = lane >> 3;
    const int rr = lane & 7;
    const int mlo = rr + (q & 1) * 8;
    const int qh = q >> 1;
    uint32_t asw[4][2];
    #pragma unroll
    for (int mi = 0; mi < 4; mi++) {
        int m = warp_m + mi * 16 + mlo;
        #pragma unroll
        for (int ks = 0; ks < 2; ks++)
            asw[mi][ks] = m * 16 + (((ks * 2 + qh) ^ (m & 3)) << 2);
    }
    const uint32_t as_base = smem_u32(Asm);
    const uint32_t bs_base = smem_u32(Bsm);

    float acc[4][4][4];
    #pragma unroll
    for (int i = 0; i < 4; i++)
        #pragma unroll
        for (int j = 0; j < 4; j++)
            #pragma unroll
            for (int r = 0; r < 4; r++) acc[i][j][r] = 0.f;

    const int T = Kh >> 5;

    auto issue = [&](int t) {
        const int s = t % STG;
        const int k0 = t * 16;
        cp16(as_base + (s * AW + aw0) * 4, &A[(size_t)(bm + am0) * lda + k0 + akq * 4]);
        cp16(as_base + (s * AW + aw1) * 4, &A[(size_t)(bm + am1) * lda + k0 + akq * 4]);
        const uint32_t* wsrc = Wf + (size_t)(t * NBLK + nblk) * 2048;
        cp16(bs_base + (s * BW + tid * 4) * 4,          &wsrc[tid * 4]);
        cp16(bs_base + (s * BW + (tid + 256) * 4) * 4,  &wsrc[(tid + 256) * 4]);
        cp_commit();
    };

    #pragma unroll
    for (int i = 0; i < STG - 1; i++) {
        if (i < T) issue(i);
        else       cp_commit();
    }

    for (int t = 0; t < T; t++) {
        cp_wait<STG - 2>();
        __syncthreads();
        const int s = t % STG;
        const uint32_t* Bst = Bsm + s * BW;

        #pragma unroll
        for (int ks = 0; ks < 2; ks++) {
            uint32_t af[4][4], bf[4][2];
            #pragma unroll
            for (int mi = 0; mi < 4; mi++)
                ldmx4(af[mi][0], af[mi][1], af[mi][2], af[mi][3],
                      as_base + (s * AW + asw[mi][ks]) * 4);
            #pragma unroll
            for (int ni = 0; ni < 4; ni++) {
                uint2 bv = *(const uint2*)&Bst[ks * 1024 + (warp_n + ni * 8) * 8 + lane * 2];
                bf[ni][0] = bv.x; bf[ni][1] = bv.y;
            }
            #pragma unroll
            for (int mi = 0; mi < 4; mi++)
                #pragma unroll
                for (int ni = 0; ni < 4; ni++)
                    mma_f16(acc[mi][ni], af[mi], bf[ni]);
        }

        if (t + STG - 1 < T) issue(t + STG - 1);
        else                 cp_commit();
    }

    #pragma unroll
    for (int mi = 0; mi < 4; mi++) {
        #pragma unroll
        for (int half = 0; half < 2; half++) {
            const int gr = bm + warp_m + mi * 16 + lg + half * 8;
            #pragma unroll
            for (int ni = 0; ni < 4; ni++) {
                const int gn = bn + warp_n + ni * 8 + lr * 2;
                float v0 = acc[mi][ni][half * 2 + 0];
                float v1 = acc[mi][ni][half * 2 + 1];
                if (bias) { v0 += bias[gn]; v1 += bias[gn + 1]; }
                if (RELU) { v0 = fmaxf(v0, 0.f); v1 = fmaxf(v1, 0.f); }
                if (OUTH) {
                    ((uint32_t*)C)[(size_t)gr * ldc + (gn >> 1)] = pack_h2(v0, v1);
                } else {
                    if (gn >= N) continue;
                    *(float2*)&C[(size_t)gr * ldc + gn] = make_float2(v0, v1);
                }
            }
        }
    }
}

// ---------------- weight prep: fragment-ordered packing ------------------------
__global__ void prep_kernel(const float* __restrict__ W2,
                            const float* __restrict__ W3,
                            const float* __restrict__ Win)
{
    int i = blockIdx.x * 256 + threadIdx.x;
    if (i < W2F_WORDS) {
        int within = i & 2047, blk = (i >> 11) & 1, t = i >> 12;
        int ks = within >> 10, n = (within >> 3) & 127;
        int lr = (within & 7) >> 1, sub = within & 1;
        int k = 2 * (t * 16 + ks * 8 + lr + sub * 4);
        int col = blk * 128 + n;
        g_w2f[i] = pack_h2(W2[k * 256 + col], W2[(k + 1) * 256 + col]);
    }
    if (i < W3F_WORDS) {
        int within = i & 2047, blk = (i >> 11) & 3, t = i >> 13;
        int ks = within >> 10, n = (within >> 3) & 127;
        int lr = (within & 7) >> 1, sub = within & 1;
        int k = 2 * (t * 16 + ks * 8 + lr + sub * 4);
        int col = blk * 128 + n;
        g_w3f[i] = pack_h2(W3[k * 512 + col], W3[(k + 1) * 512 + col]);
    }
    if (i < WINF_WORDS) {
        int within = i & 2047, blk = (i >> 11) % 10, t = i / (2048 * 10);
        int ks = within >> 10, n = (within >> 3) & 127;
        int lr = (within & 7) >> 1, sub = within & 1;
        int k = 2 * (t * 16 + ks * 8 + lr + sub * 4);
        int col = blk * 128 + n;
        g_winf[i] = (col < REST)
            ? pack_h2(Win[(size_t)k * DPROJ + DI + col],
                      Win[(size_t)(k + 1) * DPROJ + DI + col])
            : 0u;
    }
}

// ---------------- G1: fp32 fma SGEMM, packed-half output -----------------------
__global__ void sgemm1_kernel(const float* __restrict__ A,
                              const float* __restrict__ W,
                              const float* __restrict__ bias,
                              uint32_t* __restrict__ Ch)
{
    __shared__ float As[8][128];
    __shared__ float Bs[8][128];
    const int bm = blockIdx.y * 128;
    const int tid = threadIdx.x;
    const int tr = tid >> 4;
    const int tc = tid & 15;

    float acc[8][8];
    #pragma unroll
    for (int i = 0; i < 8; i++)
        #pragma unroll
        for (int j = 0; j < 8; j++) acc[i][j] = 0.f;

    for (int k0 = 0; k0 < DIN; k0 += 8) {
        {
            int e = tid * 4;
            int r = e >> 3, kk = e & 7;
            float4 av = *(const float4*)&A[(size_t)(bm + r) * DIN + k0 + kk];
            As[kk + 0][r] = av.x; As[kk + 1][r] = av.y;
            As[kk + 2][r] = av.z; As[kk + 3][r] = av.w;
        }
        {
            int e = tid * 4;
            int kk = e >> 7, n = e & 127;
            const float* wrow = W + (size_t)(k0 + kk) * 128;
            #pragma unroll
            for (int i = 0; i < 4; i++) Bs[kk][n + i] = wrow[n + i];
        }
        __syncthreads();
        #pragma unroll
        for (int kk = 0; kk < 8; kk++) {
            float4 a0 = *(const float4*)&As[kk][tr * 4];
            float4 a1 = *(const float4*)&As[kk][64 + tr * 4];
            float4 b0 = *(const float4*)&Bs[kk][tc * 4];
            float4 b1 = *(const float4*)&Bs[kk][64 + tc * 4];
            float a[8] = {a0.x,a0.y,a0.z,a0.w,a1.x,a1.y,a1.z,a1.w};
            float b[8] = {b0.x,b0.y,b0.z,b0.w,b1.x,b1.y,b1.z,b1.w};
            #pragma unroll
            for (int i = 0; i < 8; i++)
                #pragma unroll
                for (int j = 0; j < 8; j++) acc[i][j] = fmaf(a[i], b[j], acc[i][j]);
        }
        __syncthreads();
    }
    #pragma unroll
    for (int i = 0; i < 8; i++) {
        int gr = bm + ((i < 4) ? (tr * 4 + i) : (64 + tr * 4 + i - 4));
        #pragma unroll
        for (int j = 0; j < 8; j += 2) {
            int gn = (j < 4) ? (tc * 4 + j) : (64 + tc * 4 + j - 4);
            float v0 = fmaxf(acc[i][j]     + bias[gn],     0.f);
            float v1 = fmaxf(acc[i][j + 1] + bias[gn + 1], 0.f);
            Ch[(size_t)gr * 64 + (gn >> 1)] = pack_h2(v0, v1);
        }
    }
}

// ---------------- activation helpers ------------------------------------------
__device__ __forceinline__ float siluf(float x) { return x / (1.f + __expf(-x)); }
__device__ __forceinline__ float softplusf(float x) {
    return (x > 0.f) ? x + log1pf(__expf(-x)) : log1pf(__expf(x));
}

// ---------------- conv for B/C/dt channels (144 channels) ----------------------
#define LCH 64
__global__ void conv_kernel(const float* __restrict__ xbcr,
                            const float* __restrict__ conv_w,
                            const float* __restrict__ conv_b,
                            const float* __restrict__ dt_bias,
                            float* __restrict__ Bm,
                            float* __restrict__ Cm, float* __restrict__ dtp)
{
    int c  = DI + threadIdx.x;
    int b  = blockIdx.y;
    int l0 = blockIdx.z * LCH;
    if (c >= REST) return;
    const float* col = xbcr + (size_t)b * L_ * REST + c;

    if (c >= CONV_DIM) {
        int h = c - CONV_DIM;
        float bias = dt_bias[h];
        float* drow = dtp + (size_t)(b * H_ + h) * L_;
        #pragma unroll 8
        for (int l = l0; l < l0 + LCH; l++)
            drow[l] = softplusf(col[(size_t)l * REST] + bias);
        return;
    }
    float w0 = conv_w[c * 4 + 0], w1 = conv_w[c * 4 + 1];
    float w2 = conv_w[c * 4 + 2], w3 = conv_w[c * 4 + 3];
    float cb = conv_b[c];

    if (c >= DI + N_) {
        if (l0 + LCH != L_) return;
        int l = L_ - 1;
        float acc = cb + w0 * col[(size_t)(l - 3) * REST] + w1 * col[(size_t)(l - 2) * REST]
                       + w2 * col[(size_t)(l - 1) * REST] + w3 * col[(size_t)l * REST];
        Cm[b * N_ + (c - DI - N_)] = siluf(acc);
        return;
    }
    float xm3 = (l0 - 3 >= 0) ? col[(size_t)(l0 - 3) * REST] : 0.f;
    float xm2 = (l0 - 2 >= 0) ? col[(size_t)(l0 - 2) * REST] : 0.f;
    float xm1 = (l0 - 1 >= 0) ? col[(size_t)(l0 - 1) * REST] : 0.f;
    float* orow = Bm + (size_t)(b * L_ + l0) * N_ + (c - DI);
    #pragma unroll 8
    for (int l = l0; l < l0 + LCH; l++) {
        float xl = col[(size_t)l * REST];
        float acc = fmaf(w0, xm3, fmaf(w1, xm2, fmaf(w2, xm1, fmaf(w3, xl, cb))));
        *orow = siluf(acc);
        orow += N_;
        xm3 = xm2; xm2 = xm1; xm1 = xl;
    }
}

// ---------------- beta[b,t] = B_t . C_last -------------------------------------
__global__ void beta_kernel(const float* __restrict__ Bm,
                            const float* __restrict__ Cm,
                            float* __restrict__ beta)
{
    int row = blockIdx.x * 8 + (threadIdx.x >> 5);
    int b = row >> 10;
    int lane = threadIdx.x & 31;
    float s = Bm[(size_t)row * N_ + lane]      * Cm[b * N_ + lane]
            + Bm[(size_t)row * N_ + 32 + lane] * Cm[b * N_ + 32 + lane];
    #pragma unroll
    for (int o = 16; o; o >>= 1) s += __shfl_down_sync(0xffffffffu, s, o);
    if (lane == 0) beta[row] = s;
}

// ---------------- fused suffix scan + w = coef*beta + need flags ----------------
__global__ void scanw_kernel(const float* __restrict__ dtp,
                             const float* __restrict__ A_log,
                             const float* __restrict__ beta,
                             float* __restrict__ wbuf,
                             int* __restrict__ need)
{
    int bh = blockIdx.x;
    int h = bh & (H_ - 1);
    int b = bh >> 4;
    float a = expf(A_log[h]);
    __shared__ float part[256];
    __shared__ float off[256];
    const float* row = dtp + (size_t)bh * L_;
    int t0 = threadIdx.x * 4;
    float v0 = row[t0], v1 = row[t0 + 1], v2 = row[t0 + 2], v3 = row[t0 + 3];
    part[threadIdx.x] = v0 + v1 + v2 + v3;
    __syncthreads();
    if (threadIdx.x == 0) {
        float s = 0.f;
        for (int i = 255; i >= 0; i--) { off[i] = s; s += part[i]; }
    }
    __syncthreads();
    float S3 = off[threadIdx.x];
    float S2 = S3 + v3;
    float S1 = S2 + v2;
    float S0 = S1 + v1;
    const float* brow = beta + (size_t)b * L_;
    float w0v = (expf(-a * S0) * v0) * brow[t0 + 0];
    float w1v = (expf(-a * S1) * v1) * brow[t0 + 1];
    float w2v = (expf(-a * S2) * v2) * brow[t0 + 2];
    float w3v = (expf(-a * S3) * v3) * brow[t0 + 3];
    float* wrow = wbuf + (size_t)bh * L_;
    wrow[t0 + 0] = w0v; wrow[t0 + 1] = w1v;
    wrow[t0 + 2] = w2v; wrow[t0 + 3] = w3v;
    int nz = (w0v != 0.f) | (w1v != 0.f) | (w2v != 0.f) | (w3v != 0.f);
    int any = __any_sync(0xffffffffu, nz);
    int c = threadIdx.x >> 5;            // warp c covers t = 128c .. 128c+127
    if ((threadIdx.x & 31) == 0) need[bh * 8 + c] = any | (c == 7);
}

// produce flags for G4x blocks
__global__ void pflag_kernel(const int* __restrict__ need, int* __restrict__ pflag)
{
    int b = blockIdx.x;
    int tid = threadIdx.x;
    int c = tid >> 3, nb = tid & 7;
    int h0 = nb * 2, h1 = nb * 2 + 1;
    int p = need[(b * 16 + h0) * 8 + c] | need[(b * 16 + h1) * 8 + c];
    if (c < 7)
        p |= need[(b * 16 + h0) * 8 + c + 1] | need[(b * 16 + h1) * 8 + c + 1];
    pflag[(b * 8 + c) * 8 + nb] = p;
}

// ---------------- z GEMV -------------------------------------------------------
__global__ void zv_kernel(const uint32_t* __restrict__ uh,
                          const float* __restrict__ Win,
                          float* __restrict__ zb)
{
    int b  = blockIdx.y;
    int n  = blockIdx.x * 128 + threadIdx.x;
    __shared__ float us[DM];
    const uint32_t* urow = uh + (size_t)(b * L_ + L_ - 1) * 256;
    for (int i = threadIdx.x; i < 256; i += 128) {
        __half2 h = *(const __half2*)&urow[i];
        float2 f = __half22float2(h);
        us[2 * i] = f.x; us[2 * i + 1] = f.y;
    }
    __syncthreads();
    float acc = 0.f;
    #pragma unroll 8
    for (int d = 0; d < DM; d++) acc = fmaf(us[d], Win[(size_t)d * DPROJ + n], acc);
    zb[b * DI + n] = acc;
}

// ---------------- fused conv-x + time reduction (chunk-skipping) ----------------
__global__ void xy_kernel(const float* __restrict__ xbcr,
                          const float* __restrict__ conv_w,
                          const float* __restrict__ conv_b,
                          const float* __restrict__ wbuf,
                          const int* __restrict__ need,
                          const float* __restrict__ D,
                          float* __restrict__ y)
{
    int bh = blockIdx.x;
    int b = bh >> 4, h = bh & (H_ - 1);
    int tid = threadIdx.x;
    int tq = tid >> 6;
    int p  = tid & 63;
    int c  = h * P_ + p;

    __shared__ float w[L_];
    __shared__ float partial[8][64];

    const float* wrow = wbuf + (size_t)bh * L_;
    for (int i = tid; i < L_; i += 512) w[i] = wrow[i];
    __syncthreads();

    float acc = 0.f;
    if (need[bh * 8 + tq]) {
        float w0 = conv_w[c * 4 + 0], w1 = conv_w[c * 4 + 1];
        float w2 = conv_w[c * 4 + 2], w3 = conv_w[c * 4 + 3];
        float cb = conv_b[c];
        const float* col = xbcr + (size_t)b * L_ * REST + c;
        const int t0 = tq * 128;
        float xm3 = (t0 - 3 >= 0) ? col[(size_t)(t0 - 3) * REST] : 0.f;
        float xm2 = (t0 - 2 >= 0) ? col[(size_t)(t0 - 2) * REST] : 0.f;
        float xm1 = (t0 - 1 >= 0) ? col[(size_t)(t0 - 1) * REST] : 0.f;
        float vlast = 0.f;
        for (int j = 0; j < 128; j += 8) {
            float xv[8];
            #pragma unroll
            for (int i = 0; i < 8; i++)
                xv[i] = col[(size_t)(t0 + j + i) * REST];
            #pragma unroll
            for (int i = 0; i < 8; i++) {
                float v = siluf(fmaf(w0, xm3, fmaf(w1, xm2, fmaf(w2, xm1, fmaf(w3, xv[i], cb)))));
                acc = fmaf(w[t0 + j + i], v, acc);
                vlast = v;
                xm3 = xm2; xm2 = xm1; xm1 = xv[i];
            }
        }
        if (tq == 7) acc = fmaf(D[h], vlast, acc);
    }
    partial[tq][p] = acc;
    __syncthreads();
    if (tq == 0) {
        float s = 0.f;
        #pragma unroll
        for (int qi = 0; qi < 8; qi++) s += partial[qi][p];
        y[bh * P_ + p] = s;
    }
}

// ---------------- gate + rmsnorm + Wout + Wc head ------------------------------
__global__ void final_kernel(const float* __restrict__ y,
                             const float* __restrict__ zlast,
                             const float* __restrict__ norm_w,
                             const float* __restrict__ Wout,
                             const float* __restrict__ Wc,
                             const float* __restrict__ bc,
                             float* __restrict__ out)
{
    int b = blockIdx.x;
    int tid = threadIdx.x;
    __shared__ float yn[DI];
    __shared__ float seq[DM];
    __shared__ float red[256];
    float ss = 0.f;
    for (int d = tid; d < DI; d += 256) {
        float z = zlast[b * DI + d];
        float g = y[b * DI + d] * (z / (1.f + __expf(-z)));
        yn[d] = g;
        ss += g * g;
    }
    red[tid] = ss; __syncthreads();
    for (int o = 128; o; o >>= 1) { if (tid < o) red[tid] += red[tid + o]; __syncthreads(); }
    float scale = rsqrtf(red[0] / (float)DI + EPS);
    for (int d = tid; d < DI; d += 256) yn[d] *= scale * norm_w[d];
    __syncthreads();
    for (int m = tid; m < DM; m += 256) {
        float accm = 0.f;
        for (int d = 0; d < DI; d++) accm = fmaf(yn[d], Wout[(size_t)d * DM + m], accm);
        seq[m] = accm;
    }
    __syncthreads();
    if (tid < NCLS) {
        float acc = bc[tid];
        for (int m = 0; m < DM; m++) acc = fmaf(seq[m], Wc[m * NCLS + tid], acc);
        out[b * NCLS + tid] = acc;
    }
}

// ---------------- launch -------------------------------------------------------
extern "C" void kernel_launch(void* const* d_in, const int* in_sizes, int n_in,
                              void* d_out, int out_size)
{
    const float* x       = (const float*)d_in[0];
    const float* W1      = (const float*)d_in[1];
    const float* b1      = (const float*)d_in[2];
    const float* W2      = (const float*)d_in[3];
    const float* b2      = (const float*)d_in[4];
    const float* W3      = (const float*)d_in[5];
    const float* b3      = (const float*)d_in[6];
    const float* Win     = (const float*)d_in[7];
    const float* conv_w  = (const float*)d_in[8];
    const float* conv_b  = (const float*)d_in[9];
    const float* dt_bias = (const float*)d_in[10];
    const float* A_log   = (const float*)d_in[11];
    const float* Dv      = (const float*)d_in[12];
    const float* norm_w  = (const float*)d_in[13];
    const float* Wout    = (const float*)d_in[14];
    const float* Wc      = (const float*)d_in[15];
    const float* bc      = (const float*)d_in[16];
    float* out = (float*)d_out;

    uint32_t *h1h, *h2h, *uh, *w2f, *w3f, *winf;
    float *xbcr, *Bm, *Cm, *dtp, *beta, *wbuf, *yb, *zb;
    int *need, *pflag;
    cudaGetSymbolAddress((void**)&h1h,  g_h1h);
    cudaGetSymbolAddress((void**)&h2h,  g_h2h);
    cudaGetSymbolAddress((void**)&uh,   g_uh);
    cudaGetSymbolAddress((void**)&w2f,  g_w2f);
    cudaGetSymbolAddress((void**)&w3f,  g_w3f);
    cudaGetSymbolAddress((void**)&winf, g_winf);
    cudaGetSymbolAddress((void**)&xbcr, g_xbcr);
    cudaGetSymbolAddress((void**)&Bm,   g_Bm);
    cudaGetSymbolAddress((void**)&Cm,   g_Cm);
    cudaGetSymbolAddress((void**)&dtp,  g_dtp);
    cudaGetSymbolAddress((void**)&beta, g_beta);
    cudaGetSymbolAddress((void**)&wbuf, g_wbuf);
    cudaGetSymbolAddress((void**)&need, g_need);
    cudaGetSymbolAddress((void**)&pflag,g_pflag);
    cudaGetSymbolAddress((void**)&yb,   g_y);
    cudaGetSymbolAddress((void**)&zb,   g_z);

    static bool attr_done = false;
    if (!attr_done) {
        cudaFuncSetAttribute(hgemm_kernel<1,1>, cudaFuncAttributeMaxDynamicSharedMemorySize, SMEM_BYTES);
        cudaFuncSetAttribute(hgemm_kernel<0,1>, cudaFuncAttributeMaxDynamicSharedMemorySize, SMEM_BYTES);
        cudaFuncSetAttribute(hgemm_kernel<0,0>, cudaFuncAttributeMaxDynamicSharedMemorySize, SMEM_BYTES);
        attr_done = true;
    }

    // weight packing (fragment-ordered fp16)
    prep_kernel<<<(WINF_WORDS + 255) / 256, 256>>>(W2, W3, Win);
    // G1: x -> 128 (fp32 fma, packed-half output)
    sgemm1_kernel<<<dim3(1, BL/128), 256>>>(x, W1, b1, h1h);
    // G2: 128 -> 256 (NBLK=2)
    hgemm_kernel<1, 1><<<dim3(2, BL/128), 256, SMEM_BYTES>>>(
        h1h, 64, w2f, 2, b2, (float*)h2h, 128, 256, 128, 0, nullptr);
    // G3: 256 -> 512 (NBLK=4)
    hgemm_kernel<0, 1><<<dim3(4, BL/128), 256, SMEM_BYTES>>>(
        h2h, 128, w3f, 4, b3, (float*)uh, 256, 512, 256, 0, nullptr);
    // G4a: B/C/dt columns (n-blocks 8..9, NBLK=10)
    hgemm_kernel<0, 0><<<dim3(2, BL/128), 256, SMEM_BYTES>>>(
        uh, 256, winf, 10, nullptr, xbcr, REST, REST, 512, 8, nullptr);
    // conv for B/C/dt channels
    conv_kernel<<<dim3(1, B_, L_/LCH), 192>>>(xbcr, conv_w, conv_b, dt_bias, Bm, Cm, dtp);
    // beta
    beta_kernel<<<BL/8, 256>>>(Bm, Cm, beta);
    // fused suffix scan + w + need flags
    scanw_kernel<<<B_*H_, 256>>>(dtp, A_log, beta, wbuf, need);
    // produce flags for G4x
    pflag_kernel<<<B_, 64>>>(need, pflag);
    // G4b: x columns (n-blocks 0..7) with block skip
    hgemm_kernel<0, 0><<<dim3(8, BL/128), 256, SMEM_BYTES>>>(
        uh, 256, winf, 10, nullptr, xbcr, REST, REST, 512, 0, pflag);
    // z GEMV at last position
    zv_kernel<<<dim3(8, B_), 128>>>(uh, Win, zb);
    // fused conv-x + y reduction with chunk skip
    xy_kernel<<<B_*H_, 512>>>(xbcr, conv_w, conv_b, wbuf, need, Dv, yb);
    // head
    final_kernel<<<B_, 256>>>(yb, zb, norm_w, Wout, Wc, bc, out);
    (void)in_sizes; (void)n_in; (void)out_size;
}

// round 16
// speedup vs baseline: 1.1469x; 1.0049x over previous
#include <cuda_runtime.h>
#include <cuda_fp16.h>
#include <math.h>
#include <stdint.h>

// ---------------- problem constants ----------------
#define B_  32
#define L_  1024
#define DIN 16
#define DM  512
#define DI  1024          // EXP*DM
#define H_  16            // DI/P
#define P_  64
#define N_  64
#define DCONV 4
#define CONV_DIM 1152     // DI + 2N
#define DPROJ 2192        // 2*DI + 2*N + H
#define REST 1168         // CONV_DIM + H
#define NCLS 10
#define BL  (B_*L_)       // 32768
#define EPS 1e-5f

// fragment-ordered weight buffer sizes (words): T * NBLK * 2048
#define W2F_WORDS  (4  * 2  * 2048)
#define W3F_WORDS  (8  * 4  * 2048)
#define WINF_WORDS (16 * 10 * 2048)

// ---------------- scratch (static device globals; no allocations) -------------
__device__ uint32_t g_h1h[BL*64];            // [BL][64]
__device__ uint32_t g_h2h[(size_t)BL*128];   // [BL][128]
__device__ uint32_t g_uh [(size_t)BL*256];   // [BL][256]
// packed half2 weights in staged-fragment order
__device__ uint32_t g_w2f[W2F_WORDS];
__device__ uint32_t g_w3f[W3F_WORDS];
__device__ uint32_t g_winf[WINF_WORDS];
// fp32 intermediates
__device__ float g_xbcr[(size_t)BL*REST];
__device__ float g_Bm [BL*N_];
__device__ float g_Cm [B_*N_];
__device__ float g_dtp[B_*H_*L_];
__device__ float g_beta[BL];
__device__ float g_wbuf[B_*H_*L_];           // w = coef*beta
__device__ int   g_need [B_*H_*8];           // per (bh, chunk) compute flag
__device__ int   g_pflag[B_*8*8];            // per (b, chunk, nblock) produce flag
__device__ float g_y  [B_*DI];
__device__ float g_z  [B_*DI];

// ---------------- helpers ------------------------------------------------------
__device__ __forceinline__ uint32_t pack_h2(float a, float b) {
    __half2 h = __floats2half2_rn(a, b);
    return *(uint32_t*)&h;
}
__device__ __forceinline__ void mma_f16(float* c, const uint32_t* a, const uint32_t* b) {
    asm volatile(
        "mma.sync.aligned.m16n8k16.row.col.f32.f16.f16.f32 "
        "{%0,%1,%2,%3}, {%4,%5,%6,%7}, {%8,%9}, {%0,%1,%2,%3};\n"
        : "+f"(c[0]), "+f"(c[1]), "+f"(c[2]), "+f"(c[3])
        : "r"(a[0]), "r"(a[1]), "r"(a[2]), "r"(a[3]), "r"(b[0]), "r"(b[1]));
}
__device__ __forceinline__ void ldmx4(uint32_t& r0, uint32_t& r1, uint32_t& r2, uint32_t& r3,
                                      uint32_t saddr) {
    asm volatile("ldmatrix.sync.aligned.m8n8.x4.shared.b16 {%0,%1,%2,%3}, [%4];"
                 : "=r"(r0), "=r"(r1), "=r"(r2), "=r"(r3) : "r"(saddr));
}
__device__ __forceinline__ void cp16(uint32_t saddr, const void* g) {
    asm volatile("cp.async.cg.shared.global [%0], [%1], 16;\n" :: "r"(saddr), "l"(g));
}
__device__ __forceinline__ void cp_commit() { asm volatile("cp.async.commit_group;\n"); }
template<int n> __device__ __forceinline__ void cp_wait() {
    asm volatile("cp.async.wait_group %0;\n" :: "n"(n));
}
__device__ __forceinline__ uint32_t smem_u32(const void* p) {
    uint32_t a;
    asm("{ .reg .u64 t; cvta.to.shared.u64 t, %1; cvt.u32.u64 %0, t; }" : "=r"(a) : "l"(p));
    return a;
}

#define STG 6
#define AW 2048                    // A stage words (128 rows x 16 pair-words)
#define BW 2048                    // B stage words (fragment-ordered, linear)
#define SMEM_BYTES (STG * (AW + BW) * 4)   // 98304; x2 CTAs = 192KB <= 227KB

// =============================================================================
// FP16 tensor-core GEMM (m16n8k16, fp32 accum), cp.async 6-stage pipeline,
// TWO tiles per barrier (T must be even; all call sites have T in {4,8,16}).
// Invariant: prologue issues tiles 0..STG-3 (4 commits, real or empty); each
// pair iteration commits exactly 2; before pair t committed = 4+t, so
// cp_wait<STG-4> guarantees tiles t, t+1 complete. Issues at pair end target
// stages (t+4)%6, (t+5)%6 = the stages read in the PREVIOUS pair, protected
// by this pair's top __syncthreads (write-after-read safe).
// A: [M][Kh/2] packed half2 words, lda in words; XOR-swizzled smem + ldmatrix.
// Wf: fragment-ordered weights (see prep); linear 8KB stage, LDS.64 consume.
// bn0 = n-block offset; pflag = optional per-(b,chunk,nblock) CTA skip mask.
// =============================================================================
template<int RELU, int OUTH>
__global__ __launch_bounds__(256, 2) void hgemm_kernel(
    const uint32_t* __restrict__ A, int lda,
    const uint32_t* __restrict__ Wf, int NBLK,
    const float* __restrict__ bias,
    float* __restrict__ C, int ldc,
    int N, int Kh, int bn0, const int* __restrict__ pflag)
{
    if (pflag) {
        int b = blockIdx.y >> 3, chunk = blockIdx.y & 7;
        if (!pflag[(b * 8 + chunk) * 8 + blockIdx.x]) return;
    }
    extern __shared__ uint32_t smem[];
    uint32_t* Asm = smem;
    uint32_t* Bsm = smem + STG * AW;

    const int bm = blockIdx.y * 128;
    const int nblk = blockIdx.x + bn0;
    const int bn = nblk * 128;
    const int tid = threadIdx.x;
    const int warp = tid >> 5;
    const int lane = tid & 31;
    const int warp_m = (warp & 1) * 64;
    const int warp_n = (warp >> 1) * 32;
    const int lg = lane >> 2;
    const int lr = lane & 3;

    // A staging coords
    const int am0 = tid >> 2;
    const int akq = tid & 3;
    const int aw0 = am0 * 16 + ((akq ^ (am0 & 3)) << 2);
    const int am1 = am0 + 64;
    const int aw1 = am1 * 16 + ((akq ^ (am1 & 3)) << 2);

    // ldmatrix addressing for A
    const int q  = lane >> 3;
    const int rr = lane & 7;
    const int mlo = rr + (q & 1) * 8;
    const int qh = q >> 1;
    uint32_t asw[4][2];
    #pragma unroll
    for (int mi = 0; mi < 4; mi++) {
        int m = warp_m + mi * 16 + mlo;
        #pragma unroll
        for (int ks = 0; ks < 2; ks++)
            asw[mi][ks] = m * 16 + (((ks * 2 + qh) ^ (m & 3)) << 2);
    }
    const uint32_t as_base = smem_u32(Asm);
    const uint32_t bs_base = smem_u32(Bsm);

    float acc[4][4][4];
    #pragma unroll
    for (int i = 0; i < 4; i++)
        #pragma unroll
        for (int j = 0; j < 4; j++)
            #pragma unroll
            for (int r = 0; r < 4; r++) acc[i][j][r] = 0.f;

    const int T = Kh >> 5;

    auto issue = [&](int t) {
        const int s = t % STG;
        const int k0 = t * 16;
        cp16(as_base + (s * AW + aw0) * 4, &A[(size_t)(bm + am0) * lda + k0 + akq * 4]);
        cp16(as_base + (s * AW + aw1) * 4, &A[(size_t)(bm + am1) * lda + k0 + akq * 4]);
        const uint32_t* wsrc = Wf + (size_t)(t * NBLK + nblk) * 2048;
        cp16(bs_base + (s * BW + tid * 4) * 4,          &wsrc[tid * 4]);
        cp16(bs_base + (s * BW + (tid + 256) * 4) * 4,  &wsrc[(tid + 256) * 4]);
        cp_commit();
    };

    auto compute_tile = [&](int t) {
        const int s = t % STG;
        const uint32_t* Bst = Bsm + s * BW;
        #pragma unroll
        for (int ks = 0; ks < 2; ks++) {
            uint32_t af[4][4], bf[4][2];
            #pragma unroll
            for (int mi = 0; mi < 4; mi++)
                ldmx4(af[mi][0], af[mi][1], af[mi][2], af[mi][3],
                      as_base + (s * AW + asw[mi][ks]) * 4);
            #pragma unroll
            for (int ni = 0; ni < 4; ni++) {
                uint2 bv = *(const uint2*)&Bst[ks * 1024 + (warp_n + ni * 8) * 8 + lane * 2];
                bf[ni][0] = bv.x; bf[ni][1] = bv.y;
            }
            #pragma unroll
            for (int mi = 0; mi < 4; mi++)
                #pragma unroll
                for (int ni = 0; ni < 4; ni++)
                    mma_f16(acc[mi][ni], af[mi], bf[ni]);
        }
    };

    #pragma unroll
    for (int i = 0; i < STG - 2; i++) {       // tiles 0..3
        if (i < T) issue(i);
        else       cp_commit();
    }

    for (int t = 0; t < T; t += 2) {
        cp_wait<STG - 4>();
        __syncthreads();
        compute_tile(t);
        compute_tile(t + 1);
        if (t + STG - 2 < T) issue(t + STG - 2); else cp_commit();
        if (t + STG - 1 < T) issue(t + STG - 1); else cp_commit();
    }

    #pragma unroll
    for (int mi = 0; mi < 4; mi++) {
        #pragma unroll
        for (int half = 0; half < 2; half++) {
            const int gr = bm + warp_m + mi * 16 + lg + half * 8;
            #pragma unroll
            for (int ni = 0; ni < 4; ni++) {
                const int gn = bn + warp_n + ni * 8 + lr * 2;
                float v0 = acc[mi][ni][half * 2 + 0];
                float v1 = acc[mi][ni][half * 2 + 1];
                if (bias) { v0 += bias[gn]; v1 += bias[gn + 1]; }
                if (RELU) { v0 = fmaxf(v0, 0.f); v1 = fmaxf(v1, 0.f); }
                if (OUTH) {
                    ((uint32_t*)C)[(size_t)gr * ldc + (gn >> 1)] = pack_h2(v0, v1);
                } else {
                    if (gn >= N) continue;
                    *(float2*)&C[(size_t)gr * ldc + gn] = make_float2(v0, v1);
                }
            }
        }
    }
}

// ---------------- weight prep: fragment-ordered packing ------------------------
__global__ void prep_kernel(const float* __restrict__ W2,
                            const float* __restrict__ W3,
                            const float* __restrict__ Win)
{
    int i = blockIdx.x * 256 + threadIdx.x;
    if (i < W2F_WORDS) {
        int within = i & 2047, blk = (i >> 11) & 1, t = i >> 12;
        int ks = within >> 10, n = (within >> 3) & 127;
        int lr = (within & 7) >> 1, sub = within & 1;
        int k = 2 * (t * 16 + ks * 8 + lr + sub * 4);
        int col = blk * 128 + n;
        g_w2f[i] = pack_h2(W2[k * 256 + col], W2[(k + 1) * 256 + col]);
    }
    if (i < W3F_WORDS) {
        int within = i & 2047, blk = (i >> 11) & 3, t = i >> 13;
        int ks = within >> 10, n = (within >> 3) & 127;
        int lr = (within & 7) >> 1, sub = within & 1;
        int k = 2 * (t * 16 + ks * 8 + lr + sub * 4);
        int col = blk * 128 + n;
        g_w3f[i] = pack_h2(W3[k * 512 + col], W3[(k + 1) * 512 + col]);
    }
    if (i < WINF_WORDS) {
        int within = i & 2047, blk = (i >> 11) % 10, t = i / (2048 * 10);
        int ks = within >> 10, n = (within >> 3) & 127;
        int lr = (within & 7) >> 1, sub = within & 1;
        int k = 2 * (t * 16 + ks * 8 + lr + sub * 4);
        int col = blk * 128 + n;
        g_winf[i] = (col < REST)
            ? pack_h2(Win[(size_t)k * DPROJ + DI + col],
                      Win[(size_t)(k + 1) * DPROJ + DI + col])
            : 0u;
    }
}

// ---------------- G1: fp32 fma SGEMM, packed-half output -----------------------
__global__ void sgemm1_kernel(const float* __restrict__ A,
                              const float* __restrict__ W,
                              const float* __restrict__ bias,
                              uint32_t* __restrict__ Ch)
{
    __shared__ float As[8][128];
    __shared__ float Bs[8][128];
    const int bm = blockIdx.y * 128;
    const int tid = threadIdx.x;
    const int tr = tid >> 4;
    const int tc = tid & 15;

    float acc[8][8];
    #pragma unroll
    for (int i = 0; i < 8; i++)
        #pragma unroll
        for (int j = 0; j < 8; j++) acc[i][j] = 0.f;

    for (int k0 = 0; k0 < DIN; k0 += 8) {
        {
            int e = tid * 4;
            int r = e >> 3, kk = e & 7;
            float4 av = *(const float4*)&A[(size_t)(bm + r) * DIN + k0 + kk];
            As[kk + 0][r] = av.x; As[kk + 1][r] = av.y;
            As[kk + 2][r] = av.z; As[kk + 3][r] = av.w;
        }
        {
            int e = tid * 4;
            int kk = e >> 7, n = e & 127;
            const float* wrow = W + (size_t)(k0 + kk) * 128;
            #pragma unroll
            for (int i = 0; i < 4; i++) Bs[kk][n + i] = wrow[n + i];
        }
        __syncthreads();
        #pragma unroll
        for (int kk = 0; kk < 8; kk++) {
            float4 a0 = *(const float4*)&As[kk][tr * 4];
            float4 a1 = *(const float4*)&As[kk][64 + tr * 4];
            float4 b0 = *(const float4*)&Bs[kk][tc * 4];
            float4 b1 = *(const float4*)&Bs[kk][64 + tc * 4];
            float a[8] = {a0.x,a0.y,a0.z,a0.w,a1.x,a1.y,a1.z,a1.w};
            float b[8] = {b0.x,b0.y,b0.z,b0.w,b1.x,b1.y,b1.z,b1.w};
            #pragma unroll
            for (int i = 0; i < 8; i++)
                #pragma unroll
                for (int j = 0; j < 8; j++) acc[i][j] = fmaf(a[i], b[j], acc[i][j]);
        }
        __syncthreads();
    }
    #pragma unroll
    for (int i = 0; i < 8; i++) {
        int gr = bm + ((i < 4) ? (tr * 4 + i) : (64 + tr * 4 + i - 4));
        #pragma unroll
        for (int j = 0; j < 8; j += 2) {
            int gn = (j < 4) ? (tc * 4 + j) : (64 + tc * 4 + j - 4);
            float v0 = fmaxf(acc[i][j]     + bias[gn],     0.f);
            float v1 = fmaxf(acc[i][j + 1] + bias[gn + 1], 0.f);
            Ch[(size_t)gr * 64 + (gn >> 1)] = pack_h2(v0, v1);
        }
    }
}

// ---------------- activation helpers ------------------------------------------
__device__ __forceinline__ float siluf(float x) { return x / (1.f + __expf(-x)); }
__device__ __forceinline__ float softplusf(float x) {
    return (x > 0.f) ? x + log1pf(__expf(-x)) : log1pf(__expf(x));
}

// ---------------- conv for B/C/dt channels (144 channels) ----------------------
#define LCH 64
__global__ void conv_kernel(const float* __restrict__ xbcr,
                            const float* __restrict__ conv_w,
                            const float* __restrict__ conv_b,
                            const float* __restrict__ dt_bias,
                            float* __restrict__ Bm,
                            float* __restrict__ Cm, float* __restrict__ dtp)
{
    int c  = DI + threadIdx.x;
    int b  = blockIdx.y;
    int l0 = blockIdx.z * LCH;
    if (c >= REST) return;
    const float* col = xbcr + (size_t)b * L_ * REST + c;

    if (c >= CONV_DIM) {
        int h = c - CONV_DIM;
        float bias = dt_bias[h];
        float* drow = dtp + (size_t)(b * H_ + h) * L_;
        #pragma unroll 8
        for (int l = l0; l < l0 + LCH; l++)
            drow[l] = softplusf(col[(size_t)l * REST] + bias);
        return;
    }
    float w0 = conv_w[c * 4 + 0], w1 = conv_w[c * 4 + 1];
    float w2 = conv_w[c * 4 + 2], w3 = conv_w[c * 4 + 3];
    float cb = conv_b[c];

    if (c >= DI + N_) {
        if (l0 + LCH != L_) return;
        int l = L_ - 1;
        float acc = cb + w0 * col[(size_t)(l - 3) * REST] + w1 * col[(size_t)(l - 2) * REST]
                       + w2 * col[(size_t)(l - 1) * REST] + w3 * col[(size_t)l * REST];
        Cm[b * N_ + (c - DI - N_)] = siluf(acc);
        return;
    }
    float xm3 = (l0 - 3 >= 0) ? col[(size_t)(l0 - 3) * REST] : 0.f;
    float xm2 = (l0 - 2 >= 0) ? col[(size_t)(l0 - 2) * REST] : 0.f;
    float xm1 = (l0 - 1 >= 0) ? col[(size_t)(l0 - 1) * REST] : 0.f;
    float* orow = Bm + (size_t)(b * L_ + l0) * N_ + (c - DI);
    #pragma unroll 8
    for (int l = l0; l < l0 + LCH; l++) {
        float xl = col[(size_t)l * REST];
        float acc = fmaf(w0, xm3, fmaf(w1, xm2, fmaf(w2, xm1, fmaf(w3, xl, cb))));
        *orow = siluf(acc);
        orow += N_;
        xm3 = xm2; xm2 = xm1; xm1 = xl;
    }
}

// ---------------- beta[b,t] = B_t . C_last -------------------------------------
__global__ void beta_kernel(const float* __restrict__ Bm,
                            const float* __restrict__ Cm,
                            float* __restrict__ beta)
{
    int row = blockIdx.x * 8 + (threadIdx.x >> 5);
    int b = row >> 10;
    int lane = threadIdx.x & 31;
    float s = Bm[(size_t)row * N_ + lane]      * Cm[b * N_ + lane]
            + Bm[(size_t)row * N_ + 32 + lane] * Cm[b * N_ + 32 + lane];
    #pragma unroll
    for (int o = 16; o; o >>= 1) s += __shfl_down_sync(0xffffffffu, s, o);
    if (lane == 0) beta[row] = s;
}

// ---------------- fused suffix scan + w = coef*beta + need flags ----------------
__global__ void scanw_kernel(const float* __restrict__ dtp,
                             const float* __restrict__ A_log,
                             const float* __restrict__ beta,
                             float* __restrict__ wbuf,
                             int* __restrict__ need)
{
    int bh = blockIdx.x;
    int h = bh & (H_ - 1);
    int b = bh >> 4;
    float a = expf(A_log[h]);
    __shared__ float part[256];
    __shared__ float off[256];
    const float* row = dtp + (size_t)bh * L_;
    int t0 = threadIdx.x * 4;
    float v0 = row[t0], v1 = row[t0 + 1], v2 = row[t0 + 2], v3 = row[t0 + 3];
    part[threadIdx.x] = v0 + v1 + v2 + v3;
    __syncthreads();
    if (threadIdx.x == 0) {
        float s = 0.f;
        for (int i = 255; i >= 0; i--) { off[i] = s; s += part[i]; }
    }
    __syncthreads();
    float S3 = off[threadIdx.x];
    float S2 = S3 + v3;
    float S1 = S2 + v2;
    float S0 = S1 + v1;
    const float* brow = beta + (size_t)b * L_;
    float w0v = (expf(-a * S0) * v0) * brow[t0 + 0];
    float w1v = (expf(-a * S1) * v1) * brow[t0 + 1];
    float w2v = (expf(-a * S2) * v2) * brow[t0 + 2];
    float w3v = (expf(-a * S3) * v3) * brow[t0 + 3];
    float* wrow = wbuf + (size_t)bh * L_;
    wrow[t0 + 0] = w0v; wrow[t0 + 1] = w1v;
    wrow[t0 + 2] = w2v; wrow[t0 + 3] = w3v;
    int nz = (w0v != 0.f) | (w1v != 0.f) | (w2v != 0.f) | (w3v != 0.f);
    int any = __any_sync(0xffffffffu, nz);
    int c = threadIdx.x >> 5;            // warp c covers t = 128c .. 128c+127
    if ((threadIdx.x & 31) == 0) need[bh * 8 + c] = any | (c == 7);
}

// produce flags for G4x blocks
__global__ void pflag_kernel(const int* __restrict__ need, int* __restrict__ pflag)
{
    int b = blockIdx.x;
    int tid = threadIdx.x;
    int c = tid >> 3, nb = tid & 7;
    int h0 = nb * 2, h1 = nb * 2 + 1;
    int p = need[(b * 16 + h0) * 8 + c] | need[(b * 16 + h1) * 8 + c];
    if (c < 7)
        p |= need[(b * 16 + h0) * 8 + c + 1] | need[(b * 16 + h1) * 8 + c + 1];
    pflag[(b * 8 + c) * 8 + nb] = p;
}

// ---------------- z GEMV -------------------------------------------------------
__global__ void zv_kernel(const uint32_t* __restrict__ uh,
                          const float* __restrict__ Win,
                          float* __restrict__ zb)
{
    int b  = blockIdx.y;
    int n  = blockIdx.x * 128 + threadIdx.x;
    __shared__ float us[DM];
    const uint32_t* urow = uh + (size_t)(b * L_ + L_ - 1) * 256;
    for (int i = threadIdx.x; i < 256; i += 128) {
        __half2 h = *(const __half2*)&urow[i];
        float2 f = __half22float2(h);
        us[2 * i] = f.x; us[2 * i + 1] = f.y;
    }
    __syncthreads();
    float acc = 0.f;
    #pragma unroll 8
    for (int d = 0; d < DM; d++) acc = fmaf(us[d], Win[(size_t)d * DPROJ + n], acc);
    zb[b * DI + n] = acc;
}

// ---------------- fused conv-x + time reduction (chunk + j-block skipping) ------
__global__ void xy_kernel(const float* __restrict__ xbcr,
                          const float* __restrict__ conv_w,
                          const float* __restrict__ conv_b,
                          const float* __restrict__ wbuf,
                          const int* __restrict__ need,
                          const float* __restrict__ D,
                          float* __restrict__ y)
{
    int bh = blockIdx.x;
    int b = bh >> 4, h = bh & (H_ - 1);
    int tid = threadIdx.x;
    int tq = tid >> 6;
    int p  = tid & 63;
    int c  = h * P_ + p;

    __shared__ float w[L_];
    __shared__ float partial[8][64];

    const float* wrow = wbuf + (size_t)bh * L_;
    for (int i = tid; i < L_; i += 512) w[i] = wrow[i];
    __syncthreads();

    float acc = 0.f;
    if (need[bh * 8 + tq]) {
        float w0 = conv_w[c * 4 + 0], w1 = conv_w[c * 4 + 1];
        float w2 = conv_w[c * 4 + 2], w3 = conv_w[c * 4 + 3];
        float cb = conv_b[c];
        const float* col = xbcr + (size_t)b * L_ * REST + c;
        const int t0 = tq * 128;
        float xm3 = (t0 - 3 >= 0) ? col[(size_t)(t0 - 3) * REST] : 0.f;
        float xm2 = (t0 - 2 >= 0) ? col[(size_t)(t0 - 2) * REST] : 0.f;
        float xm1 = (t0 - 1 >= 0) ? col[(size_t)(t0 - 1) * REST] : 0.f;
        float vlast = 0.f;
        for (int j = 0; j < 128; j += 8) {
            float wv[8];
            #pragma unroll
            for (int i = 0; i < 8; i++) wv[i] = w[t0 + j + i];
            bool anyw = (wv[0] != 0.f) | (wv[1] != 0.f) | (wv[2] != 0.f) | (wv[3] != 0.f)
                      | (wv[4] != 0.f) | (wv[5] != 0.f) | (wv[6] != 0.f) | (wv[7] != 0.f);
            bool force = (tq == 7) && (j == 120);
            if (anyw || force) {
                float xv[8];
                #pragma unroll
                for (int i = 0; i < 8; i++)
                    xv[i] = col[(size_t)(t0 + j + i) * REST];
                #pragma unroll
                for (int i = 0; i < 8; i++) {
                    float v = siluf(fmaf(w0, xm3, fmaf(w1, xm2, fmaf(w2, xm1, fmaf(w3, xv[i], cb)))));
                    acc = fmaf(wv[i], v, acc);
                    vlast = v;
                    xm3 = xm2; xm2 = xm1; xm1 = xv[i];
                }
            } else {
                // refresh conv shift registers to the tail of this block
                xm3 = col[(size_t)(t0 + j + 5) * REST];
                xm2 = col[(size_t)(t0 + j + 6) * REST];
                xm1 = col[(size_t)(t0 + j + 7) * REST];
            }
        }
        if (tq == 7) acc = fmaf(D[h], vlast, acc);
    }
    partial[tq][p] = acc;
    __syncthreads();
    if (tq == 0) {
        float s = 0.f;
        #pragma unroll
        for (int qi = 0; qi < 8; qi++) s += partial[qi][p];
        y[bh * P_ + p] = s;
    }
}

// ---------------- gate + rmsnorm + Wout + Wc head ------------------------------
__global__ void final_kernel(const float* __restrict__ y,
                             const float* __restrict__ zlast,
                             const float* __restrict__ norm_w,
                             const float* __restrict__ Wout,
                             const float* __restrict__ Wc,
                             const float* __restrict__ bc,
                             float* __restrict__ out)
{
    int b = blockIdx.x;
    int tid = threadIdx.x;
    __shared__ float yn[DI];
    __shared__ float seq[DM];
    __shared__ float red[256];
    float ss = 0.f;
    for (int d = tid; d < DI; d += 256) {
        float z = zlast[b * DI + d];
        float g = y[b * DI + d] * (z / (1.f + __expf(-z)));
        yn[d] = g;
        ss += g * g;
    }
    red[tid] = ss; __syncthreads();
    for (int o = 128; o; o >>= 1) { if (tid < o) red[tid] += red[tid + o]; __syncthreads(); }
    float scale = rsqrtf(red[0] / (float)DI + EPS);
    for (int d = tid; d < DI; d += 256) yn[d] *= scale * norm_w[d];
    __syncthreads();
    for (int m = tid; m < DM; m += 256) {
        float accm = 0.f;
        for (int d = 0; d < DI; d++) accm = fmaf(yn[d], Wout[(size_t)d * DM + m], accm);
        seq[m] = accm;
    }
    __syncthreads();
    if (tid < NCLS) {
        float acc = bc[tid];
        for (int m = 0; m < DM; m++) acc = fmaf(seq[m], Wc[m * NCLS + tid], acc);
        out[b * NCLS + tid] = acc;
    }
}

// ---------------- launch -------------------------------------------------------
extern "C" void kernel_launch(void* const* d_in, const int* in_sizes, int n_in,
                              void* d_out, int out_size)
{
    const float* x       = (const float*)d_in[0];
    const float* W1      = (const float*)d_in[1];
    const float* b1      = (const float*)d_in[2];
    const float* W2      = (const float*)d_in[3];
    const float* b2      = (const float*)d_in[4];
    const float* W3      = (const float*)d_in[5];
    const float* b3      = (const float*)d_in[6];
    const float* Win     = (const float*)d_in[7];
    const float* conv_w  = (const float*)d_in[8];
    const float* conv_b  = (const float*)d_in[9];
    const float* dt_bias = (const float*)d_in[10];
    const float* A_log   = (const float*)d_in[11];
    const float* Dv      = (const float*)d_in[12];
    const float* norm_w  = (const float*)d_in[13];
    const float* Wout    = (const float*)d_in[14];
    const float* Wc      = (const float*)d_in[15];
    const float* bc      = (const float*)d_in[16];
    float* out = (float*)d_out;

    uint32_t *h1h, *h2h, *uh, *w2f, *w3f, *winf;
    float *xbcr, *Bm, *Cm, *dtp, *beta, *wbuf, *yb, *zb;
    int *need, *pflag;
    cudaGetSymbolAddress((void**)&h1h,  g_h1h);
    cudaGetSymbolAddress((void**)&h2h,  g_h2h);
    cudaGetSymbolAddress((void**)&uh,   g_uh);
    cudaGetSymbolAddress((void**)&w2f,  g_w2f);
    cudaGetSymbolAddress((void**)&w3f,  g_w3f);
    cudaGetSymbolAddress((void**)&winf, g_winf);
    cudaGetSymbolAddress((void**)&xbcr, g_xbcr);
    cudaGetSymbolAddress((void**)&Bm,   g_Bm);
    cudaGetSymbolAddress((void**)&Cm,   g_Cm);
    cudaGetSymbolAddress((void**)&dtp,  g_dtp);
    cudaGetSymbolAddress((void**)&beta, g_beta);
    cudaGetSymbolAddress((void**)&wbuf, g_wbuf);
    cudaGetSymbolAddress((void**)&need, g_need);
    cudaGetSymbolAddress((void**)&pflag,g_pflag);
    cudaGetSymbolAddress((void**)&yb,   g_y);
    cudaGetSymbolAddress((void**)&zb,   g_z);

    static bool attr_done = false;
    if (!attr_done) {
        cudaFuncSetAttribute(hgemm_kernel<1,1>, cudaFuncAttributeMaxDynamicSharedMemorySize, SMEM_BYTES);
        cudaFuncSetAttribute(hgemm_kernel<0,1>, cudaFuncAttributeMaxDynamicSharedMemorySize, SMEM_BYTES);
        cudaFuncSetAttribute(hgemm_kernel<0,0>, cudaFuncAttributeMaxDynamicSharedMemorySize, SMEM_BYTES);
        attr_done = true;
    }

    // weight packing (fragment-ordered fp16)
    prep_kernel<<<(WINF_WORDS + 255) / 256, 256>>>(W2, W3, Win);
    // G1: x -> 128 (fp32 fma, packed-half output)
    sgemm1_kernel<<<dim3(1, BL/128), 256>>>(x, W1, b1, h1h);
    // G2: 128 -> 256 (NBLK=2)
    hgemm_kernel<1, 1><<<dim3(2, BL/128), 256, SMEM_BYTES>>>(
        h1h, 64, w2f, 2, b2, (float*)h2h, 128, 256, 128, 0, nullptr);
    // G3: 256 -> 512 (NBLK=4)
    hgemm_kernel<0, 1><<<dim3(4, BL/128), 256, SMEM_BYTES>>>(
        h2h, 128, w3f, 4, b3, (float*)uh, 256, 512, 256, 0, nullptr);
    // G4a: B/C/dt columns (n-blocks 8..9, NBLK=10)
    hgemm_kernel<0, 0><<<dim3(2, BL/128), 256, SMEM_BYTES>>>(
        uh, 256, winf, 10, nullptr, xbcr, REST, REST, 512, 8, nullptr);
    // conv for B/C/dt channels
    conv_kernel<<<dim3(1, B_, L_/LCH), 192>>>(xbcr, conv_w, conv_b, dt_bias, Bm, Cm, dtp);
    // beta
    beta_kernel<<<BL/8, 256>>>(Bm, Cm, beta);
    // fused suffix scan + w + need flags
    scanw_kernel<<<B_*H_, 256>>>(dtp, A_log, beta, wbuf, need);
    // produce flags for G4x
    pflag_kernel<<<B_, 64>>>(need, pflag);
    // G4b: x columns (n-blocks 0..7) with block skip
    hgemm_kernel<0, 0><<<dim3(8, BL/128), 256, SMEM_BYTES>>>(
        uh, 256, winf, 10, nullptr, xbcr, REST, REST, 512, 0, pflag);
    // z GEMV at last position
    zv_kernel<<<dim3(8, B_), 128>>>(uh, Win, zb);
    // fused conv-x + y reduction with chunk + j-block skip
    xy_kernel<<<B_*H_, 512>>>(xbcr, conv_w, conv_b, wbuf, need, Dv, yb);
    // head
    final_kernel<<<B_, 256>>>(yb, zb, norm_w, Wout, Wc, bc, out);
    (void)in_sizes; (void)n_in; (void)out_size;
}